// round 1
// baseline (speedup 1.0000x reference)
#include <cuda_runtime.h>
#include <math.h>

#define BB 8
#define TT 2048
#define EE 512
#define CC 128
#define NCH 16
#define EPSV 1e-3f
#define INV_SQRT_E 0.04419417382415922f  // 512^-0.5

// ---------------- scratch (device globals; no cudaMalloc allowed) ----------
static __device__ float g_q[(size_t)BB * TT * EE];
static __device__ float g_k[(size_t)BB * TT * EE];
static __device__ float g_v[(size_t)BB * TT * EE];
static __device__ float g_attn[(size_t)BB * TT * EE];
static __device__ float g_H[(size_t)BB * NCH * EE * EE];   // local chunk states -> exclusive prefix
static __device__ float g_z[(size_t)BB * NCH * EE];        // local key colsums -> exclusive prefix
static __device__ float g_A[(size_t)BB * NCH * CC * CC];   // masked QK^T per chunk
static __device__ float g_d[(size_t)BB * NCH * CC];        // clamped denominators

// ============================================================================
// Kernel 1: q/k/v projections.  out[b,t,j] = sum_e x[b,e,t] * W[j,e] + bias[j]
// x is (B,E,T): column-friendly for the t dimension.
// grid: (T/128, E/128, B*3), 256 threads, 128x128 tile, 8x8 microtile, BK=16
// ============================================================================
__global__ __launch_bounds__(256) void proj_x_kernel(
    const float* __restrict__ x,
    const float* __restrict__ qw, const float* __restrict__ qb,
    const float* __restrict__ kw, const float* __restrict__ kb,
    const float* __restrict__ vw, const float* __restrict__ vb)
{
    int b = blockIdx.z % BB;
    int which = blockIdx.z / BB;
    const float* W;  const float* bias;  float* out;
    if (which == 0)      { W = qw; bias = qb; out = g_q; }
    else if (which == 1) { W = kw; bias = kb; out = g_k; }
    else                 { W = vw; bias = vb; out = g_v; }

    int t0 = blockIdx.x * 128;
    int j0 = blockIdx.y * 128;
    const float* xb = x + (size_t)b * EE * TT;

    __shared__ float Xs[16][128];   // [e-k][t]
    __shared__ float Ws[16][132];   // [e-k][j] (transposed store, padded)

    int tid = threadIdx.x;
    float acc[8][8];
#pragma unroll
    for (int i = 0; i < 8; i++)
#pragma unroll
        for (int j = 0; j < 8; j++) acc[i][j] = 0.f;

    for (int e0 = 0; e0 < EE; e0 += 16) {
        // X tile: rows e0+kk (stride T), cols t0..t0+127 contiguous
        {
            int kk = tid / 32;
            int tt = (tid % 32) * 4;
#pragma unroll
            for (int r = 0; r < 2; r++) {
                float4 v4 = *(const float4*)&xb[(size_t)(e0 + kk + r * 8) * TT + t0 + tt];
                *(float4*)&Xs[kk + r * 8][tt] = v4;
            }
        }
        // W tile: row j0+jj contiguous in e -> transpose into Ws
        {
            int jj = tid / 2;
            int k8 = (tid % 2) * 8;
            const float4* wr = (const float4*)&W[(size_t)(j0 + jj) * EE + e0 + k8];
            float4 w0 = wr[0], w1 = wr[1];
            Ws[k8 + 0][jj] = w0.x; Ws[k8 + 1][jj] = w0.y; Ws[k8 + 2][jj] = w0.z; Ws[k8 + 3][jj] = w0.w;
            Ws[k8 + 4][jj] = w1.x; Ws[k8 + 5][jj] = w1.y; Ws[k8 + 6][jj] = w1.z; Ws[k8 + 7][jj] = w1.w;
        }
        __syncthreads();
        int ty = tid / 16, tx = tid % 16;
#pragma unroll
        for (int kk = 0; kk < 16; kk++) {
            float a[8], bf[8];
#pragma unroll
            for (int i = 0; i < 8; i++) a[i] = Xs[kk][ty * 8 + i];
#pragma unroll
            for (int j = 0; j < 8; j++) bf[j] = Ws[kk][tx * 8 + j];
#pragma unroll
            for (int i = 0; i < 8; i++)
#pragma unroll
                for (int j = 0; j < 8; j++) acc[i][j] += a[i] * bf[j];
        }
        __syncthreads();
    }

    int ty = tid / 16, tx = tid % 16;
    float bv[8];
#pragma unroll
    for (int j = 0; j < 8; j++) bv[j] = bias[j0 + tx * 8 + j];
    float* ob = out + (size_t)b * TT * EE;
#pragma unroll
    for (int i = 0; i < 8; i++) {
        int t = t0 + ty * 8 + i;
        float* orow = &ob[(size_t)t * EE + j0 + tx * 8];
#pragma unroll
        for (int j = 0; j < 8; j++) orow[j] = acc[i][j] + bv[j];
    }
}

// ============================================================================
// Kernel 2: activations. softmax(q)*E^-0.5, exp(k), v *= toep[t]
// grid: B*T blocks, 128 threads (row of 512, 4 per thread)
// ============================================================================
__global__ __launch_bounds__(128) void act_kernel(const float* __restrict__ toep)
{
    int bt = blockIdx.x;
    int t = bt % TT;
    int tid = threadIdx.x;
    size_t base = (size_t)bt * EE;

    __shared__ float sred[4];

    // ---- q softmax ----
    float qv[4];
#pragma unroll
    for (int u = 0; u < 4; u++) qv[u] = g_q[base + tid + u * 128];
    float m = fmaxf(fmaxf(qv[0], qv[1]), fmaxf(qv[2], qv[3]));
#pragma unroll
    for (int o = 16; o; o >>= 1) m = fmaxf(m, __shfl_xor_sync(0xffffffffu, m, o));
    if ((tid & 31) == 0) sred[tid >> 5] = m;
    __syncthreads();
    m = fmaxf(fmaxf(sred[0], sred[1]), fmaxf(sred[2], sred[3]));
    __syncthreads();
    float s = 0.f;
#pragma unroll
    for (int u = 0; u < 4; u++) { qv[u] = expf(qv[u] - m); s += qv[u]; }
#pragma unroll
    for (int o = 16; o; o >>= 1) s += __shfl_xor_sync(0xffffffffu, s, o);
    if ((tid & 31) == 0) sred[tid >> 5] = s;
    __syncthreads();
    s = sred[0] + sred[1] + sred[2] + sred[3];
    float scale = INV_SQRT_E / s;
#pragma unroll
    for (int u = 0; u < 4; u++) g_q[base + tid + u * 128] = qv[u] * scale;

    // ---- k = exp(k) ----
#pragma unroll
    for (int u = 0; u < 4; u++) {
        size_t idx = base + tid + u * 128;
        g_k[idx] = expf(g_k[idx]);
    }

    // ---- v *= toep[t] ----
    float tw = toep[t];
#pragma unroll
    for (int u = 0; u < 4; u++) {
        size_t idx = base + tid + u * 128;
        g_v[idx] *= tw;
    }
}

// ============================================================================
// Kernel 3: per-chunk key colsums. g_z[b,c,e] = sum_{t in chunk} k[b,t,e]
// grid: (B*NC, E/128), 128 threads
// ============================================================================
__global__ __launch_bounds__(128) void zloc_kernel()
{
    int bc = blockIdx.x;
    int b = bc / NCH, c = bc % NCH;
    int e = blockIdx.y * 128 + threadIdx.x;
    const float* kb = g_k + ((size_t)b * TT + (size_t)c * CC) * EE + e;
    float s = 0.f;
#pragma unroll 8
    for (int t = 0; t < CC; t++) s += kb[(size_t)t * EE];
    g_z[(size_t)bc * EE + e] = s;
}

// ============================================================================
// Kernel 4: local chunk states H[b,c] = K_c^T V_c  (E x E, inner dim C=128)
// grid: (E/128, E/128, B*NC), 256 threads
// ============================================================================
__global__ __launch_bounds__(256) void hloc_kernel()
{
    int bc = blockIdx.z;
    int b = bc / NCH, c = bc % NCH;
    const float* K = g_k + ((size_t)b * TT + (size_t)c * CC) * EE;
    const float* V = g_v + ((size_t)b * TT + (size_t)c * CC) * EE;
    int r0 = blockIdx.x * 128;   // e1
    int c0 = blockIdx.y * 128;   // e2

    __shared__ float Ks[16][128];
    __shared__ float Vs[16][128];
    int tid = threadIdx.x;

    float acc[8][8];
#pragma unroll
    for (int i = 0; i < 8; i++)
#pragma unroll
        for (int j = 0; j < 8; j++) acc[i][j] = 0.f;

    for (int t0 = 0; t0 < CC; t0 += 16) {
        int kk = tid / 32;
        int cc4 = (tid % 32) * 4;
#pragma unroll
        for (int r = 0; r < 2; r++) {
            float4 kv = *(const float4*)&K[(size_t)(t0 + kk + r * 8) * EE + r0 + cc4];
            *(float4*)&Ks[kk + r * 8][cc4] = kv;
            float4 vv = *(const float4*)&V[(size_t)(t0 + kk + r * 8) * EE + c0 + cc4];
            *(float4*)&Vs[kk + r * 8][cc4] = vv;
        }
        __syncthreads();
        int ty = tid / 16, tx = tid % 16;
#pragma unroll
        for (int kk2 = 0; kk2 < 16; kk2++) {
            float a[8], bf[8];
#pragma unroll
            for (int i = 0; i < 8; i++) a[i] = Ks[kk2][ty * 8 + i];
#pragma unroll
            for (int j = 0; j < 8; j++) bf[j] = Vs[kk2][tx * 8 + j];
#pragma unroll
            for (int i = 0; i < 8; i++)
#pragma unroll
                for (int j = 0; j < 8; j++) acc[i][j] += a[i] * bf[j];
        }
        __syncthreads();
    }
    int ty = tid / 16, tx = tid % 16;
    float* Hb = g_H + (size_t)bc * EE * EE;
#pragma unroll
    for (int i = 0; i < 8; i++) {
        float* hrow = &Hb[(size_t)(r0 + ty * 8 + i) * EE + c0 + tx * 8];
#pragma unroll
        for (int j = 0; j < 8; j++) hrow[j] = acc[i][j];
    }
}

// ============================================================================
// Kernel 5: exclusive prefix over chunks (in place, per element, per batch)
// grid-stride over B*E*E, 256 threads
// ============================================================================
__global__ __launch_bounds__(256) void prefix_kernel()
{
    size_t idx = (size_t)blockIdx.x * blockDim.x + threadIdx.x;
    const size_t nper = (size_t)EE * EE;
    if (idx >= (size_t)BB * nper) return;
    size_t b = idx / nper;
    size_t off = idx % nper;
    float run = 0.f;
    float* p = g_H + b * NCH * nper + off;
#pragma unroll
    for (int c = 0; c < NCH; c++) {
        float tmp = *p;
        *p = run;
        run += tmp;
        p += nper;
    }
}

__global__ __launch_bounds__(128) void zprefix_kernel()
{
    int idx = blockIdx.x * blockDim.x + threadIdx.x;
    if (idx >= BB * EE) return;
    int b = idx / EE, off = idx % EE;
    float run = 0.f;
    float* p = g_z + (size_t)b * NCH * EE + off;
#pragma unroll
    for (int c = 0; c < NCH; c++) {
        float tmp = *p;
        *p = run;
        run += tmp;
        p += EE;
    }
}

// ============================================================================
// Kernel 6: per chunk, A = causal-mask(Q K^T), d = rowsum(A) + Q . z_excl
// grid: B*NC blocks, 256 threads, full 128x128 tile per block
// ============================================================================
__global__ __launch_bounds__(256) void qk_kernel()
{
    int bc = blockIdx.x;
    int b = bc / NCH, c = bc % NCH;
    const float* Q = g_q + ((size_t)b * TT + (size_t)c * CC) * EE;
    const float* K = g_k + ((size_t)b * TT + (size_t)c * CC) * EE;
    const float* zst = g_z + (size_t)bc * EE;   // exclusive prefix

    __shared__ float Qs[16][132];
    __shared__ float Ks[16][132];
    __shared__ float zs[16];
    __shared__ float red[128][17];
    __shared__ float dzsh[128];

    int tid = threadIdx.x;
    float acc[8][8];
#pragma unroll
    for (int i = 0; i < 8; i++)
#pragma unroll
        for (int j = 0; j < 8; j++) acc[i][j] = 0.f;
    float dz[8];
#pragma unroll
    for (int i = 0; i < 8; i++) dz[i] = 0.f;

    int ty = tid / 16, tx = tid % 16;

    for (int e0 = 0; e0 < EE; e0 += 16) {
        int row = tid / 2;
        int k8 = (tid % 2) * 8;
        {
            const float4* qr = (const float4*)&Q[(size_t)row * EE + e0 + k8];
            float4 a0 = qr[0], a1 = qr[1];
            Qs[k8 + 0][row] = a0.x; Qs[k8 + 1][row] = a0.y; Qs[k8 + 2][row] = a0.z; Qs[k8 + 3][row] = a0.w;
            Qs[k8 + 4][row] = a1.x; Qs[k8 + 5][row] = a1.y; Qs[k8 + 6][row] = a1.z; Qs[k8 + 7][row] = a1.w;
            const float4* kr = (const float4*)&K[(size_t)row * EE + e0 + k8];
            float4 b0 = kr[0], b1 = kr[1];
            Ks[k8 + 0][row] = b0.x; Ks[k8 + 1][row] = b0.y; Ks[k8 + 2][row] = b0.z; Ks[k8 + 3][row] = b0.w;
            Ks[k8 + 4][row] = b1.x; Ks[k8 + 5][row] = b1.y; Ks[k8 + 6][row] = b1.z; Ks[k8 + 7][row] = b1.w;
        }
        if (tid < 16) zs[tid] = zst[e0 + tid];
        __syncthreads();
#pragma unroll
        for (int kk = 0; kk < 16; kk++) {
            float a[8], bf[8];
#pragma unroll
            for (int i = 0; i < 8; i++) a[i] = Qs[kk][ty * 8 + i];
#pragma unroll
            for (int j = 0; j < 8; j++) bf[j] = Ks[kk][tx * 8 + j];
            float zv = zs[kk];
#pragma unroll
            for (int i = 0; i < 8; i++) {
                dz[i] += a[i] * zv;
#pragma unroll
                for (int j = 0; j < 8; j++) acc[i][j] += a[i] * bf[j];
            }
        }
        __syncthreads();
    }

    // mask (inclusive causal) + rowsum
    float* Ab = g_A + (size_t)bc * CC * CC;
#pragma unroll
    for (int i = 0; i < 8; i++) {
        int row = ty * 8 + i;
        float rs = 0.f;
#pragma unroll
        for (int j = 0; j < 8; j++) {
            int col = tx * 8 + j;
            if (col > row) acc[i][j] = 0.f;
            rs += acc[i][j];
        }
        red[row][tx] = rs;
        float* arow = &Ab[(size_t)row * CC + tx * 8];
#pragma unroll
        for (int j = 0; j < 8; j++) arow[j] = acc[i][j];
    }
    if (tx == 0) {
#pragma unroll
        for (int i = 0; i < 8; i++) dzsh[ty * 8 + i] = dz[i];
    }
    __syncthreads();
    if (tid < 128) {
        float dsum = dzsh[tid];
#pragma unroll
        for (int x = 0; x < 16; x++) dsum += red[tid][x];
        g_d[(size_t)bc * CC + tid] = fmaxf(dsum, EPSV);
    }
}

// ============================================================================
// Kernel 7: out = (A @ V_c + Q @ S_c) / d    (128 x 512 per chunk)
// grid: (E/128, B*NC), 256 threads
// ============================================================================
__global__ __launch_bounds__(256) void out_kernel()
{
    int bc = blockIdx.y;
    int b = bc / NCH, c = bc % NCH;
    int c0 = blockIdx.x * 128;
    const float* A = g_A + (size_t)bc * CC * CC;
    const float* V = g_v + ((size_t)b * TT + (size_t)c * CC) * EE;
    const float* Q = g_q + ((size_t)b * TT + (size_t)c * CC) * EE;
    const float* S = g_H + (size_t)bc * EE * EE;   // exclusive prefix now

    __shared__ float As[16][132];   // k-major A / Q operand
    __shared__ float Bs[16][128];   // V / S rows

    int tid = threadIdx.x;
    int ty = tid / 16, tx = tid % 16;
    float acc[8][8];
#pragma unroll
    for (int i = 0; i < 8; i++)
#pragma unroll
        for (int j = 0; j < 8; j++) acc[i][j] = 0.f;

    // part 1: A @ V  (K = 128)
    for (int k0 = 0; k0 < CC; k0 += 16) {
        {
            int row = tid / 2;
            int k8 = (tid % 2) * 8;
            const float4* ar = (const float4*)&A[(size_t)row * CC + k0 + k8];
            float4 a0 = ar[0], a1 = ar[1];
            As[k8 + 0][row] = a0.x; As[k8 + 1][row] = a0.y; As[k8 + 2][row] = a0.z; As[k8 + 3][row] = a0.w;
            As[k8 + 4][row] = a1.x; As[k8 + 5][row] = a1.y; As[k8 + 6][row] = a1.z; As[k8 + 7][row] = a1.w;
        }
        {
            int kk = tid / 32;
            int cc4 = (tid % 32) * 4;
#pragma unroll
            for (int r = 0; r < 2; r++) {
                float4 vv = *(const float4*)&V[(size_t)(k0 + kk + r * 8) * EE + c0 + cc4];
                *(float4*)&Bs[kk + r * 8][cc4] = vv;
            }
        }
        __syncthreads();
#pragma unroll
        for (int kk = 0; kk < 16; kk++) {
            float a[8], bf[8];
#pragma unroll
            for (int i = 0; i < 8; i++) a[i] = As[kk][ty * 8 + i];
#pragma unroll
            for (int j = 0; j < 8; j++) bf[j] = Bs[kk][tx * 8 + j];
#pragma unroll
            for (int i = 0; i < 8; i++)
#pragma unroll
                for (int j = 0; j < 8; j++) acc[i][j] += a[i] * bf[j];
        }
        __syncthreads();
    }

    // part 2: Q @ S  (K = 512)
    for (int e0 = 0; e0 < EE; e0 += 16) {
        {
            int row = tid / 2;
            int k8 = (tid % 2) * 8;
            const float4* qr = (const float4*)&Q[(size_t)row * EE + e0 + k8];
            float4 a0 = qr[0], a1 = qr[1];
            As[k8 + 0][row] = a0.x; As[k8 + 1][row] = a0.y; As[k8 + 2][row] = a0.z; As[k8 + 3][row] = a0.w;
            As[k8 + 4][row] = a1.x; As[k8 + 5][row] = a1.y; As[k8 + 6][row] = a1.z; As[k8 + 7][row] = a1.w;
        }
        {
            int kk = tid / 32;
            int cc4 = (tid % 32) * 4;
#pragma unroll
            for (int r = 0; r < 2; r++) {
                float4 sv = *(const float4*)&S[(size_t)(e0 + kk + r * 8) * EE + c0 + cc4];
                *(float4*)&Bs[kk + r * 8][cc4] = sv;
            }
        }
        __syncthreads();
#pragma unroll
        for (int kk = 0; kk < 16; kk++) {
            float a[8], bf[8];
#pragma unroll
            for (int i = 0; i < 8; i++) a[i] = As[kk][ty * 8 + i];
#pragma unroll
            for (int j = 0; j < 8; j++) bf[j] = Bs[kk][tx * 8 + j];
#pragma unroll
            for (int i = 0; i < 8; i++)
#pragma unroll
                for (int j = 0; j < 8; j++) acc[i][j] += a[i] * bf[j];
        }
        __syncthreads();
    }

    // epilogue: divide by d, write attn
    const float* drow = g_d + (size_t)bc * CC;
#pragma unroll
    for (int i = 0; i < 8; i++) {
        int row = ty * 8 + i;
        float inv = 1.0f / drow[row];
        float* orow = &g_attn[((size_t)b * TT + (size_t)c * CC + row) * EE + c0 + tx * 8];
#pragma unroll
        for (int j = 0; j < 8; j++) orow[j] = acc[i][j] * inv;
    }
}

// ============================================================================
// Kernel 8: output projection. out[b,t,j] = sum_e attn[b,t,e] * Wo[j,e] + bo[j]
// grid: (T/128, E/128, B), 256 threads
// ============================================================================
__global__ __launch_bounds__(256) void oproj_kernel(
    const float* __restrict__ ow, const float* __restrict__ ob, float* __restrict__ out)
{
    int b = blockIdx.z;
    int t0 = blockIdx.x * 128;
    int j0 = blockIdx.y * 128;
    const float* Ain = g_attn + (size_t)b * TT * EE;

    __shared__ float As[16][132];
    __shared__ float Ws[16][132];

    int tid = threadIdx.x;
    int ty = tid / 16, tx = tid % 16;
    float acc[8][8];
#pragma unroll
    for (int i = 0; i < 8; i++)
#pragma unroll
        for (int j = 0; j < 8; j++) acc[i][j] = 0.f;

    for (int e0 = 0; e0 < EE; e0 += 16) {
        {
            int row = tid / 2;
            int k8 = (tid % 2) * 8;
            const float4* ar = (const float4*)&Ain[(size_t)(t0 + row) * EE + e0 + k8];
            float4 a0 = ar[0], a1 = ar[1];
            As[k8 + 0][row] = a0.x; As[k8 + 1][row] = a0.y; As[k8 + 2][row] = a0.z; As[k8 + 3][row] = a0.w;
            As[k8 + 4][row] = a1.x; As[k8 + 5][row] = a1.y; As[k8 + 6][row] = a1.z; As[k8 + 7][row] = a1.w;
            const float4* wr = (const float4*)&ow[(size_t)(j0 + row) * EE + e0 + k8];
            float4 w0 = wr[0], w1 = wr[1];
            Ws[k8 + 0][row] = w0.x; Ws[k8 + 1][row] = w0.y; Ws[k8 + 2][row] = w0.z; Ws[k8 + 3][row] = w0.w;
            Ws[k8 + 4][row] = w1.x; Ws[k8 + 5][row] = w1.y; Ws[k8 + 6][row] = w1.z; Ws[k8 + 7][row] = w1.w;
        }
        __syncthreads();
#pragma unroll
        for (int kk = 0; kk < 16; kk++) {
            float a[8], bf[8];
#pragma unroll
            for (int i = 0; i < 8; i++) a[i] = As[kk][ty * 8 + i];
#pragma unroll
            for (int j = 0; j < 8; j++) bf[j] = Ws[kk][tx * 8 + j];
#pragma unroll
            for (int i = 0; i < 8; i++)
#pragma unroll
                for (int j = 0; j < 8; j++) acc[i][j] += a[i] * bf[j];
        }
        __syncthreads();
    }

    float bv[8];
#pragma unroll
    for (int j = 0; j < 8; j++) bv[j] = ob[j0 + tx * 8 + j];
#pragma unroll
    for (int i = 0; i < 8; i++) {
        int t = t0 + ty * 8 + i;
        float* orow = &out[((size_t)b * TT + t) * EE + j0 + tx * 8];
#pragma unroll
        for (int j = 0; j < 8; j++) orow[j] = acc[i][j] + bv[j];
    }
}

// ============================================================================
extern "C" void kernel_launch(void* const* d_in, const int* in_sizes, int n_in,
                              void* d_out, int out_size)
{
    const float* x    = (const float*)d_in[0];
    const float* toep = (const float*)d_in[1];
    const float* qw   = (const float*)d_in[2];
    const float* qb   = (const float*)d_in[3];
    const float* kw   = (const float*)d_in[4];
    const float* kb   = (const float*)d_in[5];
    const float* vw   = (const float*)d_in[6];
    const float* vb   = (const float*)d_in[7];
    const float* ow   = (const float*)d_in[8];
    const float* ob   = (const float*)d_in[9];
    float* out = (float*)d_out;

    proj_x_kernel<<<dim3(TT / 128, EE / 128, BB * 3), 256>>>(x, qw, qb, kw, kb, vw, vb);
    act_kernel<<<BB * TT, 128>>>(toep);
    zloc_kernel<<<dim3(BB * NCH, EE / 128), 128>>>();
    hloc_kernel<<<dim3(EE / 128, EE / 128, BB * NCH), 256>>>();
    prefix_kernel<<<(int)(((size_t)BB * EE * EE + 255) / 256), 256>>>();
    zprefix_kernel<<<(BB * EE + 127) / 128, 128>>>();
    qk_kernel<<<BB * NCH, 256>>>();
    out_kernel<<<dim3(EE / 128, BB * NCH), 256>>>();
    oproj_kernel<<<dim3(TT / 128, EE / 128, BB), 256>>>(ow, ob, out);
}

// round 3
// speedup vs baseline: 2.0562x; 2.0562x over previous
#include <cuda_runtime.h>
#include <cuda_bf16.h>
#include <math.h>
#include <stdint.h>

#define BB 8
#define TT 2048
#define EE 512
#define CC 128
#define NCH 16
#define EPSV 1e-3f
#define INV_SQRT_E 0.04419417382415922f  // 512^-0.5

// ---------------------------------------------------------------------------
// scratch (device globals; no cudaMalloc allowed)
// ---------------------------------------------------------------------------
static __device__ float g_q[(size_t)BB * TT * EE];   // fp32 activated q
static __device__ float g_k[(size_t)BB * TT * EE];   // fp32 exp(k)
static __device__ float g_v[(size_t)BB * TT * EE];   // fp32 toep-scaled v
static __device__ float g_H[(size_t)BB * NCH * EE * EE]; // local chunk states H'[e2,e1]

static __device__ __nv_bfloat16 xT_hi[(size_t)BB * TT * EE];
static __device__ __nv_bfloat16 xT_lo[(size_t)BB * TT * EE];
static __device__ __nv_bfloat16 w_hi[(size_t)4 * EE * EE];  // q,k,v,o
static __device__ __nv_bfloat16 w_lo[(size_t)4 * EE * EE];
static __device__ __nv_bfloat16 q_hi[(size_t)BB * TT * EE];
static __device__ __nv_bfloat16 q_lo[(size_t)BB * TT * EE];
static __device__ __nv_bfloat16 k_hi[(size_t)BB * TT * EE];
static __device__ __nv_bfloat16 k_lo[(size_t)BB * TT * EE];
static __device__ __nv_bfloat16 kT_hi[(size_t)BB * EE * TT];
static __device__ __nv_bfloat16 kT_lo[(size_t)BB * EE * TT];
static __device__ __nv_bfloat16 vT_hi[(size_t)BB * EE * TT];
static __device__ __nv_bfloat16 vT_lo[(size_t)BB * EE * TT];
static __device__ __nv_bfloat16 S_hi[(size_t)BB * NCH * EE * EE]; // exclusive-prefix states
static __device__ __nv_bfloat16 S_lo[(size_t)BB * NCH * EE * EE];
static __device__ __nv_bfloat16 A_hi[(size_t)BB * NCH * CC * CC]; // masked QK^T
static __device__ __nv_bfloat16 A_lo[(size_t)BB * NCH * CC * CC];
static __device__ __nv_bfloat16 at_hi[(size_t)BB * TT * EE];      // attn output (split)
static __device__ __nv_bfloat16 at_lo[(size_t)BB * TT * EE];

static __device__ float g_z[(size_t)BB * NCH * EE];   // key colsums -> exclusive prefix
static __device__ float g_rs[(size_t)BB * NCH * CC];  // rowsum of masked A
static __device__ float g_dz[(size_t)BB * NCH * CC];  // q . z_excl

// ---------------------------------------------------------------------------
// helpers
// ---------------------------------------------------------------------------
__device__ __forceinline__ uint32_t smem_u32(const void* p) {
    uint32_t a;
    asm("{ .reg .u64 t; cvta.to.shared.u64 t, %1; cvt.u32.u64 %0, t; }" : "=r"(a) : "l"(p));
    return a;
}

#define SWZ128(x) ((x) ^ (((x) >> 3) & 0x70))

__device__ __forceinline__ void ldm4(uint32_t* r, uint32_t addr) {
    asm volatile("ldmatrix.sync.aligned.m8n8.x4.shared.b16 {%0,%1,%2,%3}, [%4];"
                 : "=r"(r[0]), "=r"(r[1]), "=r"(r[2]), "=r"(r[3]) : "r"(addr));
}

__device__ __forceinline__ void mma16816(float* c, const uint32_t* a, uint32_t b0, uint32_t b1) {
    asm volatile(
        "mma.sync.aligned.m16n8k16.row.col.f32.bf16.bf16.f32 "
        "{%0,%1,%2,%3}, {%4,%5,%6,%7}, {%8,%9}, {%0,%1,%2,%3};"
        : "+f"(c[0]), "+f"(c[1]), "+f"(c[2]), "+f"(c[3])
        : "r"(a[0]), "r"(a[1]), "r"(a[2]), "r"(a[3]), "r"(b0), "r"(b1));
}

__device__ __forceinline__ void split_pair(float x, float y, uint32_t& hi, uint32_t& lo) {
    __nv_bfloat16 hx = __float2bfloat16(x), hy = __float2bfloat16(y);
    __nv_bfloat16 lx = __float2bfloat16(x - __bfloat162float(hx));
    __nv_bfloat16 ly = __float2bfloat16(y - __bfloat162float(hy));
    hi = (uint32_t)__bfloat16_as_ushort(hx) | ((uint32_t)__bfloat16_as_ushort(hy) << 16);
    lo = (uint32_t)__bfloat16_as_ushort(lx) | ((uint32_t)__bfloat16_as_ushort(ly) << 16);
}

// ---------------------------------------------------------------------------
// block GEMM: C[m,n] += sum_k (Ahi+Alo)[m,k]*(Bhi+Blo)[n,k]
// block 128x128, BK=64, 256 threads, 8 warps (4 m x 2 n), warp tile 32x64
// acc[mt][n8t][4]: mt in 0..1 (m16 tiles), n8t in 0..7 (n8 tiles)
// ---------------------------------------------------------------------------
#define OFF_AHI 0
#define OFF_ALO 16384
#define OFF_BHI 32768
#define OFF_BLO 49152
#define SMEM_BYTES 65536

__device__ __forceinline__ void gemm_block(
    float (&acc)[2][8][4],
    uint32_t su, char* sm,
    const __nv_bfloat16* __restrict__ ah, const __nv_bfloat16* __restrict__ al,
    const __nv_bfloat16* __restrict__ bh, const __nv_bfloat16* __restrict__ bl,
    int lda, int ldb, int nk)
{
    const int tid = threadIdx.x;
    const int lane = tid & 31, wid = tid >> 5;
    const int warp_m = wid >> 1, warp_n = wid & 1;
    const int q = lane >> 3, r8 = lane & 7;
    // ldmatrix lane geometry
    const int a_rowoff = warp_m * 32 + (q & 1) * 8 + r8;   // row within block (mt adds 16)
    const int a_kcadd  = q >> 1;                            // 16B-chunk add within k16
    const int b_nbase  = warp_n * 64 + (q >> 1) * 8 + r8;   // n-row within block (nt adds 16)
    const int b_kcadd  = q & 1;

    const uint32_t a_base = su + OFF_AHI + (uint32_t)(a_rowoff * 128);
    const uint32_t b_base = su + OFF_BHI + (uint32_t)(b_nbase * 128);

    for (int kc = 0; kc < nk; kc++) {
        int kofs = kc * 64;
#pragma unroll
        for (int u = 0; u < 4; u++) {
            int ch = tid + u * 256;
            int row = ch >> 3, c16 = ch & 7;
            uint32_t so = SWZ128((uint32_t)(row * 128 + c16 * 16));
            size_t goa = (size_t)row * lda + kofs + c16 * 8;
            size_t gob = (size_t)row * ldb + kofs + c16 * 8;
            *(uint4*)(sm + OFF_AHI + so) = *(const uint4*)(ah + goa);
            *(uint4*)(sm + OFF_ALO + so) = *(const uint4*)(al + goa);
            *(uint4*)(sm + OFF_BHI + so) = *(const uint4*)(bh + gob);
            *(uint4*)(sm + OFF_BLO + so) = *(const uint4*)(bl + gob);
        }
        __syncthreads();
#pragma unroll
        for (int ks = 0; ks < 4; ks++) {
            uint32_t Ah[2][4], Al[2][4];
            uint32_t a_ch = (uint32_t)(((ks * 2 + a_kcadd) ^ r8) * 16);
#pragma unroll
            for (int mt = 0; mt < 2; mt++) {
                uint32_t addr = a_base + (uint32_t)(mt * 2048) + a_ch;
                ldm4(Ah[mt], addr);
                ldm4(Al[mt], addr + (OFF_ALO - OFF_AHI));
            }
            uint32_t b_ch = (uint32_t)(((ks * 2 + b_kcadd) ^ r8) * 16);
#pragma unroll
            for (int nt = 0; nt < 4; nt++) {
                uint32_t Bh[4], Bl[4];
                uint32_t baddr = b_base + (uint32_t)(nt * 2048) + b_ch;
                ldm4(Bh, baddr);
                ldm4(Bl, baddr + (OFF_BLO - OFF_BHI));
#pragma unroll
                for (int mt = 0; mt < 2; mt++) {
#pragma unroll
                    for (int h = 0; h < 2; h++) {
                        float* c = acc[mt][nt * 2 + h];
                        mma16816(c, Ah[mt], Bh[2 * h], Bh[2 * h + 1]);
                        mma16816(c, Ah[mt], Bl[2 * h], Bl[2 * h + 1]);
                        mma16816(c, Al[mt], Bh[2 * h], Bh[2 * h + 1]);
                    }
                }
            }
        }
        __syncthreads();
    }
}

#define ZERO_ACC(acc) do { \
    _Pragma("unroll") for (int _i = 0; _i < 2; _i++) \
    _Pragma("unroll") for (int _j = 0; _j < 8; _j++) \
    _Pragma("unroll") for (int _l = 0; _l < 4; _l++) acc[_i][_j][_l] = 0.f; \
} while (0)

// epilogue geometry: rows = warp_m*32 + mt*16 + h*8 + g; cols = warp_n*64 + n8t*8 + tg*2
#define EPI_VARS \
    const int lane = threadIdx.x & 31, wid = threadIdx.x >> 5; \
    const int warp_m = wid >> 1, warp_n = wid & 1; \
    const int g = lane >> 2, tg = lane & 3;

// ---------------------------------------------------------------------------
// GEMM wrapper kernels
// ---------------------------------------------------------------------------

// q/k/v projections: D[t,j] = sum_e xT[t,e] * W[j,e] + bias -> fp32 g_q/g_k/g_v
__global__ __launch_bounds__(256) void gemm_proj_kernel(
    const float* __restrict__ qb, const float* __restrict__ kb, const float* __restrict__ vb)
{
    extern __shared__ char sm[];
    uint32_t su = smem_u32(sm);
    int m0 = blockIdx.x * 128, n0 = blockIdx.y * 128, which = blockIdx.z;

    float acc[2][8][4];
    ZERO_ACC(acc);
    gemm_block(acc, su, sm,
               xT_hi + (size_t)m0 * EE, xT_lo + (size_t)m0 * EE,
               w_hi + (size_t)which * EE * EE + (size_t)n0 * EE,
               w_lo + (size_t)which * EE * EE + (size_t)n0 * EE,
               EE, EE, 8);

    const float* bias = (which == 0) ? qb : (which == 1) ? kb : vb;
    float* out = (which == 0) ? g_q : (which == 1) ? g_k : g_v;
    EPI_VARS;
#pragma unroll
    for (int mt = 0; mt < 2; mt++)
#pragma unroll
        for (int h = 0; h < 2; h++) {
            int row = m0 + warp_m * 32 + mt * 16 + h * 8 + g;
#pragma unroll
            for (int nt = 0; nt < 8; nt++) {
                int col = n0 + warp_n * 64 + nt * 8 + tg * 2;
                float2 o;
                o.x = acc[mt][nt][2 * h] + bias[col];
                o.y = acc[mt][nt][2 * h + 1] + bias[col + 1];
                *(float2*)&out[(size_t)row * EE + col] = o;
            }
        }
}

// chunk states: H'[e2,e1] = sum_t vT[e2,t] * kT[e1,t]  -> fp32 g_H
__global__ __launch_bounds__(256) void gemm_hloc_kernel()
{
    extern __shared__ char sm[];
    uint32_t su = smem_u32(sm);
    int m0 = blockIdx.x * 128, n0 = blockIdx.y * 128;
    int bc = blockIdx.z, b = bc / NCH, c = bc % NCH;

    float acc[2][8][4];
    ZERO_ACC(acc);
    gemm_block(acc, su, sm,
               vT_hi + ((size_t)b * EE + m0) * TT + (size_t)c * CC,
               vT_lo + ((size_t)b * EE + m0) * TT + (size_t)c * CC,
               kT_hi + ((size_t)b * EE + n0) * TT + (size_t)c * CC,
               kT_lo + ((size_t)b * EE + n0) * TT + (size_t)c * CC,
               TT, TT, 2);

    float* Hb = g_H + (size_t)bc * EE * EE;
    EPI_VARS;
#pragma unroll
    for (int mt = 0; mt < 2; mt++)
#pragma unroll
        for (int h = 0; h < 2; h++) {
            int row = m0 + warp_m * 32 + mt * 16 + h * 8 + g;
#pragma unroll
            for (int nt = 0; nt < 8; nt++) {
                int col = n0 + warp_n * 64 + nt * 8 + tg * 2;
                float2 o = make_float2(acc[mt][nt][2 * h], acc[mt][nt][2 * h + 1]);
                *(float2*)&Hb[(size_t)row * EE + col] = o;
            }
        }
}

// A = causal-mask(Q K^T): rowsum -> g_rs, split bf16 -> A_hi/A_lo
__global__ __launch_bounds__(256) void gemm_qk_kernel()
{
    extern __shared__ char sm[];
    __shared__ float s_rs[128][2];
    uint32_t su = smem_u32(sm);
    int bc = blockIdx.x, b = bc / NCH, c = bc % NCH;
    size_t base = ((size_t)b * TT + (size_t)c * CC) * EE;

    float acc[2][8][4];
    ZERO_ACC(acc);
    gemm_block(acc, su, sm, q_hi + base, q_lo + base, k_hi + base, k_lo + base, EE, EE, 8);

    EPI_VARS;
    __nv_bfloat16* Ah = A_hi + (size_t)bc * CC * CC;
    __nv_bfloat16* Al = A_lo + (size_t)bc * CC * CC;
#pragma unroll
    for (int mt = 0; mt < 2; mt++)
#pragma unroll
        for (int h = 0; h < 2; h++) {
            int row = warp_m * 32 + mt * 16 + h * 8 + g;
            float rs = 0.f;
#pragma unroll
            for (int nt = 0; nt < 8; nt++) {
                int col = warp_n * 64 + nt * 8 + tg * 2;
                float v0 = acc[mt][nt][2 * h], v1 = acc[mt][nt][2 * h + 1];
                if (col > row) v0 = 0.f;
                if (col + 1 > row) v1 = 0.f;
                rs += v0 + v1;
                uint32_t hi, lo;
                split_pair(v0, v1, hi, lo);
                *(uint32_t*)&Ah[(size_t)row * CC + col] = hi;
                *(uint32_t*)&Al[(size_t)row * CC + col] = lo;
            }
            rs += __shfl_xor_sync(0xffffffffu, rs, 1);
            rs += __shfl_xor_sync(0xffffffffu, rs, 2);
            if (tg == 0) s_rs[row][warp_n] = rs;
        }
    __syncthreads();
    if (threadIdx.x < 128)
        g_rs[(size_t)bc * CC + threadIdx.x] = s_rs[threadIdx.x][0] + s_rs[threadIdx.x][1];
}

// out = (A @ V_c + Q @ S_c) / d, split -> at_hi/at_lo
__global__ __launch_bounds__(256) void gemm_out_kernel()
{
    extern __shared__ char sm[];
    uint32_t su = smem_u32(sm);
    int n0 = blockIdx.x * 128;
    int bc = blockIdx.y, b = bc / NCH, c = bc % NCH;

    float acc[2][8][4];
    ZERO_ACC(acc);
    // phase 1: A(128x128) @ V_c
    gemm_block(acc, su, sm,
               A_hi + (size_t)bc * CC * CC, A_lo + (size_t)bc * CC * CC,
               vT_hi + ((size_t)b * EE + n0) * TT + (size_t)c * CC,
               vT_lo + ((size_t)b * EE + n0) * TT + (size_t)c * CC,
               CC, TT, 2);
    // phase 2: Q(128x512) @ S'(e2, e1)
    size_t qbase = ((size_t)b * TT + (size_t)c * CC) * EE;
    gemm_block(acc, su, sm,
               q_hi + qbase, q_lo + qbase,
               S_hi + (size_t)bc * EE * EE + (size_t)n0 * EE,
               S_lo + (size_t)bc * EE * EE + (size_t)n0 * EE,
               EE, EE, 8);

    EPI_VARS;
#pragma unroll
    for (int mt = 0; mt < 2; mt++)
#pragma unroll
        for (int h = 0; h < 2; h++) {
            int row = warp_m * 32 + mt * 16 + h * 8 + g;
            float d = fmaxf(g_rs[(size_t)bc * CC + row] + g_dz[(size_t)bc * CC + row], EPSV);
            float inv = 1.0f / d;
            size_t ob = ((size_t)b * TT + (size_t)c * CC + row) * EE + n0;
#pragma unroll
            for (int nt = 0; nt < 8; nt++) {
                int col = warp_n * 64 + nt * 8 + tg * 2;
                float v0 = acc[mt][nt][2 * h] * inv, v1 = acc[mt][nt][2 * h + 1] * inv;
                uint32_t hi, lo;
                split_pair(v0, v1, hi, lo);
                *(uint32_t*)&at_hi[ob + col] = hi;
                *(uint32_t*)&at_lo[ob + col] = lo;
            }
        }
}

// output projection -> d_out
__global__ __launch_bounds__(256) void gemm_oproj_kernel(
    const float* __restrict__ ob_bias, float* __restrict__ outp)
{
    extern __shared__ char sm[];
    uint32_t su = smem_u32(sm);
    int m0 = blockIdx.x * 128, n0 = blockIdx.y * 128;

    float acc[2][8][4];
    ZERO_ACC(acc);
    gemm_block(acc, su, sm,
               at_hi + (size_t)m0 * EE, at_lo + (size_t)m0 * EE,
               w_hi + (size_t)3 * EE * EE + (size_t)n0 * EE,
               w_lo + (size_t)3 * EE * EE + (size_t)n0 * EE,
               EE, EE, 8);

    EPI_VARS;
#pragma unroll
    for (int mt = 0; mt < 2; mt++)
#pragma unroll
        for (int h = 0; h < 2; h++) {
            int row = m0 + warp_m * 32 + mt * 16 + h * 8 + g;
#pragma unroll
            for (int nt = 0; nt < 8; nt++) {
                int col = n0 + warp_n * 64 + nt * 8 + tg * 2;
                float2 o;
                o.x = acc[mt][nt][2 * h] + ob_bias[col];
                o.y = acc[mt][nt][2 * h + 1] + ob_bias[col + 1];
                *(float2*)&outp[(size_t)row * EE + col] = o;
            }
        }
}

// ---------------------------------------------------------------------------
// conversion / elementwise kernels
// ---------------------------------------------------------------------------
__global__ __launch_bounds__(256) void conv_w_kernel(
    const float* __restrict__ qw, const float* __restrict__ kw,
    const float* __restrict__ vw, const float* __restrict__ ow)
{
    size_t idx = (size_t)blockIdx.x * 256 + threadIdx.x;
    if (idx >= (size_t)4 * EE * EE) return;
    int which = (int)(idx / ((size_t)EE * EE));
    size_t rem = idx % ((size_t)EE * EE);
    const float* w = (which == 0) ? qw : (which == 1) ? kw : (which == 2) ? vw : ow;
    float x = w[rem];
    __nv_bfloat16 h = __float2bfloat16(x);
    w_hi[idx] = h;
    w_lo[idx] = __float2bfloat16(x - __bfloat162float(h));
}

// x (B,E,T) fp32 -> xT (B,T,E) bf16 split
__global__ __launch_bounds__(256) void conv_xT_kernel(const float* __restrict__ x)
{
    __shared__ float ts[32][33];
    int b = blockIdx.z;
    int t0 = blockIdx.x * 32, e0 = blockIdx.y * 32;
    int tx = threadIdx.x, ty = threadIdx.y;  // (32,8)
    const float* xb = x + (size_t)b * EE * TT;
#pragma unroll
    for (int i = 0; i < 4; i++)
        ts[ty + i * 8][tx] = xb[(size_t)(e0 + ty + i * 8) * TT + t0 + tx];
    __syncthreads();
    size_t ob = (size_t)b * TT * EE;
#pragma unroll
    for (int i = 0; i < 4; i++) {
        float val = ts[tx][ty + i * 8];
        __nv_bfloat16 h = __float2bfloat16(val);
        size_t o = ob + (size_t)(t0 + ty + i * 8) * EE + e0 + tx;
        xT_hi[o] = h;
        xT_lo[o] = __float2bfloat16(val - __bfloat162float(h));
    }
}

// activations + split
__global__ __launch_bounds__(128) void act_kernel(const float* __restrict__ toep)
{
    int bt = blockIdx.x;
    int t = bt % TT;
    int tid = threadIdx.x;
    size_t base = (size_t)bt * EE;
    __shared__ float sred[4];

    float qv[4];
#pragma unroll
    for (int u = 0; u < 4; u++) qv[u] = g_q[base + tid + u * 128];
    float m = fmaxf(fmaxf(qv[0], qv[1]), fmaxf(qv[2], qv[3]));
#pragma unroll
    for (int o = 16; o; o >>= 1) m = fmaxf(m, __shfl_xor_sync(0xffffffffu, m, o));
    if ((tid & 31) == 0) sred[tid >> 5] = m;
    __syncthreads();
    m = fmaxf(fmaxf(sred[0], sred[1]), fmaxf(sred[2], sred[3]));
    __syncthreads();
    float s = 0.f;
#pragma unroll
    for (int u = 0; u < 4; u++) { qv[u] = expf(qv[u] - m); s += qv[u]; }
#pragma unroll
    for (int o = 16; o; o >>= 1) s += __shfl_xor_sync(0xffffffffu, s, o);
    if ((tid & 31) == 0) sred[tid >> 5] = s;
    __syncthreads();
    s = sred[0] + sred[1] + sred[2] + sred[3];
    float scale = INV_SQRT_E / s;
#pragma unroll
    for (int u = 0; u < 4; u++) {
        size_t idx = base + tid + u * 128;
        float val = qv[u] * scale;
        g_q[idx] = val;
        __nv_bfloat16 h = __float2bfloat16(val);
        q_hi[idx] = h;
        q_lo[idx] = __float2bfloat16(val - __bfloat162float(h));
    }
#pragma unroll
    for (int u = 0; u < 4; u++) {
        size_t idx = base + tid + u * 128;
        float val = expf(g_k[idx]);
        g_k[idx] = val;
        __nv_bfloat16 h = __float2bfloat16(val);
        k_hi[idx] = h;
        k_lo[idx] = __float2bfloat16(val - __bfloat162float(h));
    }
    float tw = toep[t];
#pragma unroll
    for (int u = 0; u < 4; u++) {
        size_t idx = base + tid + u * 128;
        g_v[idx] *= tw;
    }
}

// fp32 (B,T,E) -> bf16 split (B,E,T); which 0=k,1=v
__global__ __launch_bounds__(256) void tsplit_kernel()
{
    __shared__ float ts[32][33];
    int which = blockIdx.z / BB;
    int b = blockIdx.z % BB;
    int t0 = blockIdx.x * 32, e0 = blockIdx.y * 32;
    int tx = threadIdx.x, ty = threadIdx.y;
    const float* in = (which == 0 ? g_k : g_v) + (size_t)b * TT * EE;
    __nv_bfloat16* ohi = (which == 0 ? kT_hi : vT_hi) + (size_t)b * EE * TT;
    __nv_bfloat16* olo = (which == 0 ? kT_lo : vT_lo) + (size_t)b * EE * TT;
#pragma unroll
    for (int i = 0; i < 4; i++)
        ts[ty + i * 8][tx] = in[(size_t)(t0 + ty + i * 8) * EE + e0 + tx];
    __syncthreads();
#pragma unroll
    for (int i = 0; i < 4; i++) {
        float val = ts[tx][ty + i * 8];
        __nv_bfloat16 h = __float2bfloat16(val);
        size_t o = (size_t)(e0 + ty + i * 8) * TT + t0 + tx;
        ohi[o] = h;
        olo[o] = __float2bfloat16(val - __bfloat162float(h));
    }
}

__global__ __launch_bounds__(128) void zloc_kernel()
{
    int bc = blockIdx.x;
    int b = bc / NCH, c = bc % NCH;
    int e = blockIdx.y * 128 + threadIdx.x;
    const float* kb = g_k + ((size_t)b * TT + (size_t)c * CC) * EE + e;
    float s = 0.f;
#pragma unroll 8
    for (int t = 0; t < CC; t++) s += kb[(size_t)t * EE];
    g_z[(size_t)bc * EE + e] = s;
}

__global__ __launch_bounds__(128) void zprefix_kernel()
{
    int idx = blockIdx.x * blockDim.x + threadIdx.x;
    if (idx >= BB * EE) return;
    int b = idx / EE, off = idx % EE;
    float run = 0.f;
    float* p = g_z + (size_t)b * NCH * EE + off;
#pragma unroll
    for (int c = 0; c < NCH; c++) {
        float tmp = *p; *p = run; run += tmp; p += EE;
    }
}

// exclusive prefix over chunks of g_H -> split bf16 states S_hi/S_lo
__global__ __launch_bounds__(256) void prefix_kernel()
{
    size_t idx = (size_t)blockIdx.x * 256 + threadIdx.x;
    const size_t nper = (size_t)EE * EE;
    if (idx >= (size_t)BB * nper) return;
    size_t b = idx / nper, off = idx % nper;
    float run = 0.f;
#pragma unroll
    for (int c = 0; c < NCH; c++) {
        size_t p = (b * NCH + c) * nper + off;
        float h = g_H[p];
        __nv_bfloat16 rh = __float2bfloat16(run);
        S_hi[p] = rh;
        S_lo[p] = __float2bfloat16(run - __bfloat162float(rh));
        run += h;
    }
}

// dz[b,c,i] = sum_e q[b, c*128+i, e] * z_excl[b,c,e]
__global__ __launch_bounds__(256) void dz_kernel()
{
    int bc = blockIdx.x;
    int b = bc / NCH, c = bc % NCH;
    int w = threadIdx.x >> 5, lane = threadIdx.x & 31;
    const float* z = g_z + (size_t)bc * EE;
#pragma unroll
    for (int it = 0; it < 16; it++) {
        int i = it * 8 + w;
        const float* qr = g_q + ((size_t)b * TT + (size_t)c * CC + i) * EE;
        float s = 0.f;
#pragma unroll 4
        for (int j = lane; j < EE; j += 32) s += qr[j] * z[j];
#pragma unroll
        for (int o = 16; o; o >>= 1) s += __shfl_xor_sync(0xffffffffu, s, o);
        if (lane == 0) g_dz[(size_t)bc * CC + i] = s;
    }
}

// ---------------------------------------------------------------------------
extern "C" void kernel_launch(void* const* d_in, const int* in_sizes, int n_in,
                              void* d_out, int out_size)
{
    const float* x    = (const float*)d_in[0];
    const float* toep = (const float*)d_in[1];
    const float* qw   = (const float*)d_in[2];
    const float* qb   = (const float*)d_in[3];
    const float* kw   = (const float*)d_in[4];
    const float* kb   = (const float*)d_in[5];
    const float* vw   = (const float*)d_in[6];
    const float* vb   = (const float*)d_in[7];
    const float* ow   = (const float*)d_in[8];
    const float* ob   = (const float*)d_in[9];
    float* out = (float*)d_out;

    static int attr_done = 0;
    if (!attr_done) {
        cudaFuncSetAttribute(gemm_proj_kernel,  cudaFuncAttributeMaxDynamicSharedMemorySize, SMEM_BYTES);
        cudaFuncSetAttribute(gemm_hloc_kernel,  cudaFuncAttributeMaxDynamicSharedMemorySize, SMEM_BYTES);
        cudaFuncSetAttribute(gemm_qk_kernel,    cudaFuncAttributeMaxDynamicSharedMemorySize, SMEM_BYTES);
        cudaFuncSetAttribute(gemm_out_kernel,   cudaFuncAttributeMaxDynamicSharedMemorySize, SMEM_BYTES);
        cudaFuncSetAttribute(gemm_oproj_kernel, cudaFuncAttributeMaxDynamicSharedMemorySize, SMEM_BYTES);
        attr_done = 1;
    }

    conv_w_kernel<<<(int)(((size_t)4 * EE * EE + 255) / 256), 256>>>(qw, kw, vw, ow);
    conv_xT_kernel<<<dim3(TT / 32, EE / 32, BB), dim3(32, 8)>>>(x);

    gemm_proj_kernel<<<dim3(BB * TT / 128, EE / 128, 3), 256, SMEM_BYTES>>>(qb, kb, vb);
    act_kernel<<<BB * TT, 128>>>(toep);
    tsplit_kernel<<<dim3(TT / 32, EE / 32, BB * 2), dim3(32, 8)>>>();

    zloc_kernel<<<dim3(BB * NCH, EE / 128), 128>>>();
    zprefix_kernel<<<(BB * EE + 127) / 128, 128>>>();

    gemm_hloc_kernel<<<dim3(EE / 128, EE / 128, BB * NCH), 256, SMEM_BYTES>>>();
    prefix_kernel<<<(int)(((size_t)BB * EE * EE + 255) / 256), 256>>>();

    gemm_qk_kernel<<<BB * NCH, 256, SMEM_BYTES>>>();
    dz_kernel<<<BB * NCH, 256>>>();
    gemm_out_kernel<<<dim3(EE / 128, BB * NCH), 256, SMEM_BYTES>>>();
    gemm_oproj_kernel<<<dim3(BB * TT / 128, EE / 128), 256, SMEM_BYTES>>>(ob, out);
}

// round 4
// speedup vs baseline: 2.3789x; 1.1570x over previous
#include <cuda_runtime.h>
#include <cuda_bf16.h>
#include <math.h>
#include <stdint.h>

#define BB 8
#define TT 2048
#define EE 512
#define CC 128
#define NCH 16
#define EPSV 1e-3f
#define INV_SQRT_E 0.04419417382415922f  // 512^-0.5

// ---------------------------------------------------------------------------
// scratch (device globals; no cudaMalloc allowed)
// ---------------------------------------------------------------------------
static __device__ float g_q[(size_t)BB * TT * EE];   // fp32 q (pre-softmax)

static __device__ __nv_bfloat16 xT_hi[(size_t)BB * TT * EE];
static __device__ __nv_bfloat16 xT_lo[(size_t)BB * TT * EE];
static __device__ __nv_bfloat16 w_hi[(size_t)4 * EE * EE];  // q,k,v,o
static __device__ __nv_bfloat16 w_lo[(size_t)4 * EE * EE];
static __device__ __nv_bfloat16 q_hi[(size_t)BB * TT * EE];
static __device__ __nv_bfloat16 q_lo[(size_t)BB * TT * EE];
static __device__ __nv_bfloat16 k_hi[(size_t)BB * TT * EE];
static __device__ __nv_bfloat16 k_lo[(size_t)BB * TT * EE];
static __device__ __nv_bfloat16 kT_hi[(size_t)BB * EE * TT];
static __device__ __nv_bfloat16 kT_lo[(size_t)BB * EE * TT];
static __device__ __nv_bfloat16 vT_hi[(size_t)BB * EE * TT];
static __device__ __nv_bfloat16 vT_lo[(size_t)BB * EE * TT];
static __device__ __nv_bfloat16 H_hi[(size_t)BB * NCH * EE * EE]; // local chunk states
static __device__ __nv_bfloat16 H_lo[(size_t)BB * NCH * EE * EE];
static __device__ __nv_bfloat16 S_hi[(size_t)BB * NCH * EE * EE]; // exclusive-prefix states
static __device__ __nv_bfloat16 S_lo[(size_t)BB * NCH * EE * EE];
static __device__ __nv_bfloat16 A_hi[(size_t)BB * NCH * CC * CC]; // masked QK^T
static __device__ __nv_bfloat16 A_lo[(size_t)BB * NCH * CC * CC];
static __device__ __nv_bfloat16 at_hi[(size_t)BB * TT * EE];      // attn output (split)
static __device__ __nv_bfloat16 at_lo[(size_t)BB * TT * EE];

static __device__ float g_z[(size_t)BB * NCH * EE];   // key colsums -> exclusive prefix
static __device__ float g_rs[(size_t)BB * NCH * CC];  // rowsum of masked A
static __device__ float g_dz[(size_t)BB * NCH * CC];  // q . z_excl

// ---------------------------------------------------------------------------
// helpers
// ---------------------------------------------------------------------------
__device__ __forceinline__ uint32_t smem_u32(const void* p) {
    uint32_t a;
    asm("{ .reg .u64 t; cvta.to.shared.u64 t, %1; cvt.u32.u64 %0, t; }" : "=r"(a) : "l"(p));
    return a;
}

#define SWZ128(x) ((x) ^ (((x) >> 3) & 0x70))

__device__ __forceinline__ void ldm4(uint32_t* r, uint32_t addr) {
    asm volatile("ldmatrix.sync.aligned.m8n8.x4.shared.b16 {%0,%1,%2,%3}, [%4];"
                 : "=r"(r[0]), "=r"(r[1]), "=r"(r[2]), "=r"(r[3]) : "r"(addr));
}

__device__ __forceinline__ void mma16816(float* c, const uint32_t* a, uint32_t b0, uint32_t b1) {
    asm volatile(
        "mma.sync.aligned.m16n8k16.row.col.f32.bf16.bf16.f32 "
        "{%0,%1,%2,%3}, {%4,%5,%6,%7}, {%8,%9}, {%0,%1,%2,%3};"
        : "+f"(c[0]), "+f"(c[1]), "+f"(c[2]), "+f"(c[3])
        : "r"(a[0]), "r"(a[1]), "r"(a[2]), "r"(a[3]), "r"(b0), "r"(b1));
}

__device__ __forceinline__ void cpa16(uint32_t dst, const void* src) {
    asm volatile("cp.async.cg.shared.global [%0], [%1], 16;" :: "r"(dst), "l"(src));
}

__device__ __forceinline__ void split_pair(float x, float y, uint32_t& hi, uint32_t& lo) {
    __nv_bfloat16 hx = __float2bfloat16(x), hy = __float2bfloat16(y);
    __nv_bfloat16 lx = __float2bfloat16(x - __bfloat162float(hx));
    __nv_bfloat16 ly = __float2bfloat16(y - __bfloat162float(hy));
    hi = (uint32_t)__bfloat16_as_ushort(hx) | ((uint32_t)__bfloat16_as_ushort(hy) << 16);
    lo = (uint32_t)__bfloat16_as_ushort(lx) | ((uint32_t)__bfloat16_as_ushort(ly) << 16);
}

// ---------------------------------------------------------------------------
// block GEMM: C[m,n] += sum_k (Ahi+Alo)[m,k]*(Bhi+Blo)[n,k]
// block 128x128, BK=64, 256 threads, 8 warps (4 m x 2 n), warp tile 32x64
// ---------------------------------------------------------------------------
#define OFF_AHI 0
#define OFF_ALO 16384
#define OFF_BHI 32768
#define OFF_BLO 49152
#define SMEM_BYTES 65536

__device__ __forceinline__ void gemm_block(
    float (&acc)[2][8][4],
    uint32_t su, char* sm,
    const __nv_bfloat16* __restrict__ ah, const __nv_bfloat16* __restrict__ al,
    const __nv_bfloat16* __restrict__ bh, const __nv_bfloat16* __restrict__ bl,
    int lda, int ldb, int nk)
{
    const int tid = threadIdx.x;
    const int lane = tid & 31, wid = tid >> 5;
    const int warp_m = wid >> 1, warp_n = wid & 1;
    const int q = lane >> 3, r8 = lane & 7;
    const int a_rowoff = warp_m * 32 + (q & 1) * 8 + r8;
    const int a_kcadd  = q >> 1;
    const int b_nbase  = warp_n * 64 + (q >> 1) * 8 + r8;
    const int b_kcadd  = q & 1;

    const uint32_t a_base = su + OFF_AHI + (uint32_t)(a_rowoff * 128);
    const uint32_t b_base = su + OFF_BHI + (uint32_t)(b_nbase * 128);

    for (int kc = 0; kc < nk; kc++) {
        int kofs = kc * 64;
#pragma unroll
        for (int u = 0; u < 4; u++) {
            int ch = tid + u * 256;
            int row = ch >> 3, c16 = ch & 7;
            uint32_t so = SWZ128((uint32_t)(row * 128 + c16 * 16));
            size_t goa = (size_t)row * lda + kofs + c16 * 8;
            size_t gob = (size_t)row * ldb + kofs + c16 * 8;
            cpa16(su + OFF_AHI + so, ah + goa);
            cpa16(su + OFF_ALO + so, al + goa);
            cpa16(su + OFF_BHI + so, bh + gob);
            cpa16(su + OFF_BLO + so, bl + gob);
        }
        asm volatile("cp.async.commit_group;" ::: "memory");
        asm volatile("cp.async.wait_group 0;" ::: "memory");
        __syncthreads();
#pragma unroll
        for (int ks = 0; ks < 4; ks++) {
            uint32_t Ah[2][4], Al[2][4];
            uint32_t a_ch = (uint32_t)(((ks * 2 + a_kcadd) ^ r8) * 16);
#pragma unroll
            for (int mt = 0; mt < 2; mt++) {
                uint32_t addr = a_base + (uint32_t)(mt * 2048) + a_ch;
                ldm4(Ah[mt], addr);
                ldm4(Al[mt], addr + (OFF_ALO - OFF_AHI));
            }
            uint32_t b_ch = (uint32_t)(((ks * 2 + b_kcadd) ^ r8) * 16);
#pragma unroll
            for (int nt = 0; nt < 4; nt++) {
                uint32_t Bh[4], Bl[4];
                uint32_t baddr = b_base + (uint32_t)(nt * 2048) + b_ch;
                ldm4(Bh, baddr);
                ldm4(Bl, baddr + (OFF_BLO - OFF_BHI));
#pragma unroll
                for (int mt = 0; mt < 2; mt++) {
#pragma unroll
                    for (int h = 0; h < 2; h++) {
                        float* c = acc[mt][nt * 2 + h];
                        mma16816(c, Ah[mt], Bh[2 * h], Bh[2 * h + 1]);
                        mma16816(c, Ah[mt], Bl[2 * h], Bl[2 * h + 1]);
                        mma16816(c, Al[mt], Bh[2 * h], Bh[2 * h + 1]);
                    }
                }
            }
        }
        __syncthreads();
    }
}

#define ZERO_ACC(acc) do { \
    _Pragma("unroll") for (int _i = 0; _i < 2; _i++) \
    _Pragma("unroll") for (int _j = 0; _j < 8; _j++) \
    _Pragma("unroll") for (int _l = 0; _l < 4; _l++) acc[_i][_j][_l] = 0.f; \
} while (0)

#define EPI_VARS \
    const int tid = threadIdx.x; \
    const int lane = tid & 31, wid = tid >> 5; \
    const int warp_m = wid >> 1, warp_n = wid & 1; \
    const int g = lane >> 2, tg = lane & 3;

#define TPAD 136   // padded row length (elems) for transpose buffer (16B-mult)

// ---------------------------------------------------------------------------
// q/k/v projections: D[t,j] = sum_e xT[t,e] * W[j,e] + bias
//   which=0 (q): fp32 row-major -> g_q (softmax later in act)
//   which=1 (k): exp -> split row-major (k_hi/k_lo), transpose -> kT, colsum -> g_z
//   which=2 (v): *toep[t] -> transpose -> vT split only
// ---------------------------------------------------------------------------
__global__ __launch_bounds__(256) void gemm_proj_kernel(
    const float* __restrict__ qb, const float* __restrict__ kb,
    const float* __restrict__ vb, const float* __restrict__ toep)
{
    extern __shared__ char sm[];
    __shared__ float zred[4][128];
    uint32_t su = smem_u32(sm);
    int m0 = blockIdx.x * 128, n0 = blockIdx.y * 128, which = blockIdx.z;

    float acc[2][8][4];
    ZERO_ACC(acc);
    gemm_block(acc, su, sm,
               xT_hi + (size_t)m0 * EE, xT_lo + (size_t)m0 * EE,
               w_hi + (size_t)which * EE * EE + (size_t)n0 * EE,
               w_lo + (size_t)which * EE * EE + (size_t)n0 * EE,
               EE, EE, 8);

    EPI_VARS;
    const int b = m0 / TT, t0g = m0 % TT;
    __nv_bfloat16* buf = (__nv_bfloat16*)sm;   // reuse gemm smem for transpose

    if (which == 0) {
        // q: bias add, fp32 row-major
#pragma unroll
        for (int mt = 0; mt < 2; mt++)
#pragma unroll
            for (int h = 0; h < 2; h++) {
                int row = m0 + warp_m * 32 + mt * 16 + h * 8 + g;
#pragma unroll
                for (int nt = 0; nt < 8; nt++) {
                    int col = n0 + warp_n * 64 + nt * 8 + tg * 2;
                    float2 o;
                    o.x = acc[mt][nt][2 * h] + qb[col];
                    o.y = acc[mt][nt][2 * h + 1] + qb[col + 1];
                    *(float2*)&g_q[(size_t)row * EE + col] = o;
                }
            }
        return;
    }

    if (which == 1) {
        // k: exp + row-major split + colsum partials
        float cs[16];
#pragma unroll
        for (int i = 0; i < 16; i++) cs[i] = 0.f;
#pragma unroll
        for (int mt = 0; mt < 2; mt++)
#pragma unroll
            for (int h = 0; h < 2; h++) {
                int row = warp_m * 32 + mt * 16 + h * 8 + g;
#pragma unroll
                for (int nt = 0; nt < 8; nt++) {
                    int col = warp_n * 64 + nt * 8 + tg * 2;
                    float v0 = expf(acc[mt][nt][2 * h]     + kb[n0 + col]);
                    float v1 = expf(acc[mt][nt][2 * h + 1] + kb[n0 + col + 1]);
                    acc[mt][nt][2 * h] = v0;
                    acc[mt][nt][2 * h + 1] = v1;
                    cs[nt * 2] += v0;
                    cs[nt * 2 + 1] += v1;
                    uint32_t hi, lo;
                    split_pair(v0, v1, hi, lo);
                    *(uint32_t*)&k_hi[(size_t)(m0 + row) * EE + n0 + col] = hi;
                    *(uint32_t*)&k_lo[(size_t)(m0 + row) * EE + n0 + col] = lo;
                }
            }
#pragma unroll
        for (int i = 0; i < 16; i++) {
            cs[i] += __shfl_xor_sync(0xffffffffu, cs[i], 4);
            cs[i] += __shfl_xor_sync(0xffffffffu, cs[i], 8);
            cs[i] += __shfl_xor_sync(0xffffffffu, cs[i], 16);
        }
        if (g == 0) {
#pragma unroll
            for (int nt = 0; nt < 8; nt++) {
                int col = warp_n * 64 + nt * 8 + tg * 2;
                zred[warp_m][col] = cs[nt * 2];
                zred[warp_m][col + 1] = cs[nt * 2 + 1];
            }
        }
    } else {
        // v: toeplitz scale (row-dependent)
#pragma unroll
        for (int mt = 0; mt < 2; mt++)
#pragma unroll
            for (int h = 0; h < 2; h++) {
                int row = warp_m * 32 + mt * 16 + h * 8 + g;
                float tw = toep[t0g + row];
#pragma unroll
                for (int nt = 0; nt < 8; nt++) {
                    int col = warp_n * 64 + nt * 8 + tg * 2;
                    acc[mt][nt][2 * h]     = (acc[mt][nt][2 * h]     + vb[n0 + col]) * tw;
                    acc[mt][nt][2 * h + 1] = (acc[mt][nt][2 * h + 1] + vb[n0 + col + 1]) * tw;
                }
            }
    }

    __nv_bfloat16* dsth = (which == 1) ? kT_hi : vT_hi;
    __nv_bfloat16* dstl = (which == 1) ? kT_lo : vT_lo;

    // pass 1: hi transpose
#pragma unroll
    for (int mt = 0; mt < 2; mt++)
#pragma unroll
        for (int h = 0; h < 2; h++) {
            int row = warp_m * 32 + mt * 16 + h * 8 + g;
#pragma unroll
            for (int nt = 0; nt < 8; nt++) {
                int col = warp_n * 64 + nt * 8 + tg * 2;
                buf[(size_t)col * TPAD + row] = __float2bfloat16(acc[mt][nt][2 * h]);
                buf[(size_t)(col + 1) * TPAD + row] = __float2bfloat16(acc[mt][nt][2 * h + 1]);
            }
        }
    __syncthreads();
    if (which == 1 && tid < 128) {
        int bc = b * NCH + t0g / CC;
        g_z[(size_t)bc * EE + n0 + tid] =
            zred[0][tid] + zred[1][tid] + zred[2][tid] + zred[3][tid];
    }
    {
        int e = tid >> 1, th = (tid & 1) * 64;
        const uint4* src = (const uint4*)(buf + (size_t)e * TPAD + th);
        uint4* dst = (uint4*)(dsth + ((size_t)b * EE + n0 + e) * TT + t0g + th);
#pragma unroll
        for (int i = 0; i < 8; i++) dst[i] = src[i];
    }
    __syncthreads();
    // pass 2: lo transpose
#pragma unroll
    for (int mt = 0; mt < 2; mt++)
#pragma unroll
        for (int h = 0; h < 2; h++) {
            int row = warp_m * 32 + mt * 16 + h * 8 + g;
#pragma unroll
            for (int nt = 0; nt < 8; nt++) {
                int col = warp_n * 64 + nt * 8 + tg * 2;
                float v0 = acc[mt][nt][2 * h], v1 = acc[mt][nt][2 * h + 1];
                buf[(size_t)col * TPAD + row] =
                    __float2bfloat16(v0 - __bfloat162float(__float2bfloat16(v0)));
                buf[(size_t)(col + 1) * TPAD + row] =
                    __float2bfloat16(v1 - __bfloat162float(__float2bfloat16(v1)));
            }
        }
    __syncthreads();
    {
        int e = tid >> 1, th = (tid & 1) * 64;
        const uint4* src = (const uint4*)(buf + (size_t)e * TPAD + th);
        uint4* dst = (uint4*)(dstl + ((size_t)b * EE + n0 + e) * TT + t0g + th);
#pragma unroll
        for (int i = 0; i < 8; i++) dst[i] = src[i];
    }
}

// ---------------------------------------------------------------------------
// chunk states: H'[e2,e1] = sum_t vT[e2,t] * kT[e1,t] -> split bf16 H
// ---------------------------------------------------------------------------
__global__ __launch_bounds__(256) void gemm_hloc_kernel()
{
    extern __shared__ char sm[];
    uint32_t su = smem_u32(sm);
    int m0 = blockIdx.x * 128, n0 = blockIdx.y * 128;
    int bc = blockIdx.z, b = bc / NCH, c = bc % NCH;

    float acc[2][8][4];
    ZERO_ACC(acc);
    gemm_block(acc, su, sm,
               vT_hi + ((size_t)b * EE + m0) * TT + (size_t)c * CC,
               vT_lo + ((size_t)b * EE + m0) * TT + (size_t)c * CC,
               kT_hi + ((size_t)b * EE + n0) * TT + (size_t)c * CC,
               kT_lo + ((size_t)b * EE + n0) * TT + (size_t)c * CC,
               TT, TT, 2);

    __nv_bfloat16* Hh = H_hi + (size_t)bc * EE * EE;
    __nv_bfloat16* Hl = H_lo + (size_t)bc * EE * EE;
    EPI_VARS;
    (void)tid; (void)lane;
#pragma unroll
    for (int mt = 0; mt < 2; mt++)
#pragma unroll
        for (int h = 0; h < 2; h++) {
            int row = m0 + warp_m * 32 + mt * 16 + h * 8 + g;
#pragma unroll
            for (int nt = 0; nt < 8; nt++) {
                int col = n0 + warp_n * 64 + nt * 8 + tg * 2;
                uint32_t hi, lo;
                split_pair(acc[mt][nt][2 * h], acc[mt][nt][2 * h + 1], hi, lo);
                *(uint32_t*)&Hh[(size_t)row * EE + col] = hi;
                *(uint32_t*)&Hl[(size_t)row * EE + col] = lo;
            }
        }
}

// ---------------------------------------------------------------------------
// A = causal-mask(Q K^T): rowsum -> g_rs, split bf16 -> A_hi/A_lo
// ---------------------------------------------------------------------------
__global__ __launch_bounds__(256) void gemm_qk_kernel()
{
    extern __shared__ char sm[];
    __shared__ float s_rs[128][2];
    uint32_t su = smem_u32(sm);
    int bc = blockIdx.x, b = bc / NCH, c = bc % NCH;
    size_t base = ((size_t)b * TT + (size_t)c * CC) * EE;

    float acc[2][8][4];
    ZERO_ACC(acc);
    gemm_block(acc, su, sm, q_hi + base, q_lo + base, k_hi + base, k_lo + base, EE, EE, 8);

    EPI_VARS;
    (void)lane;
    __nv_bfloat16* Ah = A_hi + (size_t)bc * CC * CC;
    __nv_bfloat16* Al = A_lo + (size_t)bc * CC * CC;
#pragma unroll
    for (int mt = 0; mt < 2; mt++)
#pragma unroll
        for (int h = 0; h < 2; h++) {
            int row = warp_m * 32 + mt * 16 + h * 8 + g;
            float rs = 0.f;
#pragma unroll
            for (int nt = 0; nt < 8; nt++) {
                int col = warp_n * 64 + nt * 8 + tg * 2;
                float v0 = acc[mt][nt][2 * h], v1 = acc[mt][nt][2 * h + 1];
                if (col > row) v0 = 0.f;
                if (col + 1 > row) v1 = 0.f;
                rs += v0 + v1;
                uint32_t hi, lo;
                split_pair(v0, v1, hi, lo);
                *(uint32_t*)&Ah[(size_t)row * CC + col] = hi;
                *(uint32_t*)&Al[(size_t)row * CC + col] = lo;
            }
            rs += __shfl_xor_sync(0xffffffffu, rs, 1);
            rs += __shfl_xor_sync(0xffffffffu, rs, 2);
            if (tg == 0) s_rs[row][warp_n] = rs;
        }
    __syncthreads();
    if (tid < 128)
        g_rs[(size_t)bc * CC + tid] = s_rs[tid][0] + s_rs[tid][1];
}

// ---------------------------------------------------------------------------
// out = (A @ V_c + Q @ S_c) / d, split -> at_hi/at_lo
// ---------------------------------------------------------------------------
__global__ __launch_bounds__(256) void gemm_out_kernel()
{
    extern __shared__ char sm[];
    uint32_t su = smem_u32(sm);
    int n0 = blockIdx.x * 128;
    int bc = blockIdx.y, b = bc / NCH, c = bc % NCH;

    float acc[2][8][4];
    ZERO_ACC(acc);
    gemm_block(acc, su, sm,
               A_hi + (size_t)bc * CC * CC, A_lo + (size_t)bc * CC * CC,
               vT_hi + ((size_t)b * EE + n0) * TT + (size_t)c * CC,
               vT_lo + ((size_t)b * EE + n0) * TT + (size_t)c * CC,
               CC, TT, 2);
    size_t qbase = ((size_t)b * TT + (size_t)c * CC) * EE;
    gemm_block(acc, su, sm,
               q_hi + qbase, q_lo + qbase,
               S_hi + (size_t)bc * EE * EE + (size_t)n0 * EE,
               S_lo + (size_t)bc * EE * EE + (size_t)n0 * EE,
               EE, EE, 8);

    EPI_VARS;
    (void)tid; (void)lane;
#pragma unroll
    for (int mt = 0; mt < 2; mt++)
#pragma unroll
        for (int h = 0; h < 2; h++) {
            int row = warp_m * 32 + mt * 16 + h * 8 + g;
            float d = fmaxf(g_rs[(size_t)bc * CC + row] + g_dz[(size_t)bc * CC + row], EPSV);
            float inv = 1.0f / d;
            size_t ob = ((size_t)b * TT + (size_t)c * CC + row) * EE + n0;
#pragma unroll
            for (int nt = 0; nt < 8; nt++) {
                int col = warp_n * 64 + nt * 8 + tg * 2;
                uint32_t hi, lo;
                split_pair(acc[mt][nt][2 * h] * inv, acc[mt][nt][2 * h + 1] * inv, hi, lo);
                *(uint32_t*)&at_hi[ob + col] = hi;
                *(uint32_t*)&at_lo[ob + col] = lo;
            }
        }
}

// ---------------------------------------------------------------------------
// output projection -> d_out
// ---------------------------------------------------------------------------
__global__ __launch_bounds__(256) void gemm_oproj_kernel(
    const float* __restrict__ ob_bias, float* __restrict__ outp)
{
    extern __shared__ char sm[];
    uint32_t su = smem_u32(sm);
    int m0 = blockIdx.x * 128, n0 = blockIdx.y * 128;

    float acc[2][8][4];
    ZERO_ACC(acc);
    gemm_block(acc, su, sm,
               at_hi + (size_t)m0 * EE, at_lo + (size_t)m0 * EE,
               w_hi + (size_t)3 * EE * EE + (size_t)n0 * EE,
               w_lo + (size_t)3 * EE * EE + (size_t)n0 * EE,
               EE, EE, 8);

    EPI_VARS;
    (void)tid; (void)lane;
#pragma unroll
    for (int mt = 0; mt < 2; mt++)
#pragma unroll
        for (int h = 0; h < 2; h++) {
            int row = m0 + warp_m * 32 + mt * 16 + h * 8 + g;
#pragma unroll
            for (int nt = 0; nt < 8; nt++) {
                int col = n0 + warp_n * 64 + nt * 8 + tg * 2;
                float2 o;
                o.x = acc[mt][nt][2 * h] + ob_bias[col];
                o.y = acc[mt][nt][2 * h + 1] + ob_bias[col + 1];
                *(float2*)&outp[(size_t)row * EE + col] = o;
            }
        }
}

// ---------------------------------------------------------------------------
// conversion / elementwise kernels
// ---------------------------------------------------------------------------
__global__ __launch_bounds__(256) void conv_w_kernel(
    const float* __restrict__ qw, const float* __restrict__ kw,
    const float* __restrict__ vw, const float* __restrict__ ow)
{
    size_t idx = (size_t)blockIdx.x * 256 + threadIdx.x;
    if (idx >= (size_t)4 * EE * EE) return;
    int which = (int)(idx / ((size_t)EE * EE));
    size_t rem = idx % ((size_t)EE * EE);
    const float* w = (which == 0) ? qw : (which == 1) ? kw : (which == 2) ? vw : ow;
    float x = w[rem];
    __nv_bfloat16 h = __float2bfloat16(x);
    w_hi[idx] = h;
    w_lo[idx] = __float2bfloat16(x - __bfloat162float(h));
}

// x (B,E,T) fp32 -> xT (B,T,E) bf16 split
__global__ __launch_bounds__(256) void conv_xT_kernel(const float* __restrict__ x)
{
    __shared__ float ts[32][33];
    int b = blockIdx.z;
    int t0 = blockIdx.x * 32, e0 = blockIdx.y * 32;
    int tx = threadIdx.x, ty = threadIdx.y;  // (32,8)
    const float* xb = x + (size_t)b * EE * TT;
#pragma unroll
    for (int i = 0; i < 4; i++)
        ts[ty + i * 8][tx] = xb[(size_t)(e0 + ty + i * 8) * TT + t0 + tx];
    __syncthreads();
    size_t ob = (size_t)b * TT * EE;
#pragma unroll
    for (int i = 0; i < 4; i++) {
        float val = ts[tx][ty + i * 8];
        __nv_bfloat16 h = __float2bfloat16(val);
        size_t o = ob + (size_t)(t0 + ty + i * 8) * EE + e0 + tx;
        xT_hi[o] = h;
        xT_lo[o] = __float2bfloat16(val - __bfloat162float(h));
    }
}

// q softmax + split
__global__ __launch_bounds__(128) void act_kernel()
{
    int bt = blockIdx.x;
    int tid = threadIdx.x;
    size_t base = (size_t)bt * EE;
    __shared__ float sred[4];

    float qv[4];
#pragma unroll
    for (int u = 0; u < 4; u++) qv[u] = g_q[base + tid + u * 128];
    float m = fmaxf(fmaxf(qv[0], qv[1]), fmaxf(qv[2], qv[3]));
#pragma unroll
    for (int o = 16; o; o >>= 1) m = fmaxf(m, __shfl_xor_sync(0xffffffffu, m, o));
    if ((tid & 31) == 0) sred[tid >> 5] = m;
    __syncthreads();
    m = fmaxf(fmaxf(sred[0], sred[1]), fmaxf(sred[2], sred[3]));
    __syncthreads();
    float s = 0.f;
#pragma unroll
    for (int u = 0; u < 4; u++) { qv[u] = expf(qv[u] - m); s += qv[u]; }
#pragma unroll
    for (int o = 16; o; o >>= 1) s += __shfl_xor_sync(0xffffffffu, s, o);
    if ((tid & 31) == 0) sred[tid >> 5] = s;
    __syncthreads();
    s = sred[0] + sred[1] + sred[2] + sred[3];
    float scale = INV_SQRT_E / s;
#pragma unroll
    for (int u = 0; u < 4; u++) {
        size_t idx = base + tid + u * 128;
        float val = qv[u] * scale;
        __nv_bfloat16 h = __float2bfloat16(val);
        q_hi[idx] = h;
        q_lo[idx] = __float2bfloat16(val - __bfloat162float(h));
    }
}

__global__ __launch_bounds__(128) void zprefix_kernel()
{
    int idx = blockIdx.x * blockDim.x + threadIdx.x;
    if (idx >= BB * EE) return;
    int b = idx / EE, off = idx % EE;
    float run = 0.f;
    float* p = g_z + (size_t)b * NCH * EE + off;
#pragma unroll
    for (int c = 0; c < NCH; c++) {
        float tmp = *p; *p = run; run += tmp; p += EE;
    }
}

// exclusive prefix over chunks of split H -> split S
__global__ __launch_bounds__(256) void prefix_kernel()
{
    size_t idx = (size_t)blockIdx.x * 256 + threadIdx.x;
    const size_t nper = (size_t)EE * EE;
    if (idx >= (size_t)BB * nper) return;
    size_t b = idx / nper, off = idx % nper;
    float run = 0.f;
#pragma unroll
    for (int c = 0; c < NCH; c++) {
        size_t p = (b * NCH + c) * nper + off;
        float h = __bfloat162float(H_hi[p]) + __bfloat162float(H_lo[p]);
        __nv_bfloat16 rh = __float2bfloat16(run);
        S_hi[p] = rh;
        S_lo[p] = __float2bfloat16(run - __bfloat162float(rh));
        run += h;
    }
}

// dz[b,c,i] = sum_e q[b, c*128+i, e] * z_excl[b,c,e]   (q from split)
__global__ __launch_bounds__(256) void dz_kernel()
{
    int bc = blockIdx.x;
    int b = bc / NCH, c = bc % NCH;
    int w = threadIdx.x >> 5, lane = threadIdx.x & 31;
    const float* z = g_z + (size_t)bc * EE;
#pragma unroll
    for (int it = 0; it < 16; it++) {
        int i = it * 8 + w;
        size_t qrow = ((size_t)b * TT + (size_t)c * CC + i) * EE;
        float s = 0.f;
#pragma unroll 4
        for (int j = lane; j < EE; j += 32) {
            float qv = __bfloat162float(q_hi[qrow + j]) + __bfloat162float(q_lo[qrow + j]);
            s += qv * z[j];
        }
#pragma unroll
        for (int o = 16; o; o >>= 1) s += __shfl_xor_sync(0xffffffffu, s, o);
        if (lane == 0) g_dz[(size_t)bc * CC + i] = s;
    }
}

// ---------------------------------------------------------------------------
extern "C" void kernel_launch(void* const* d_in, const int* in_sizes, int n_in,
                              void* d_out, int out_size)
{
    const float* x    = (const float*)d_in[0];
    const float* toep = (const float*)d_in[1];
    const float* qw   = (const float*)d_in[2];
    const float* qb   = (const float*)d_in[3];
    const float* kw   = (const float*)d_in[4];
    const float* kb   = (const float*)d_in[5];
    const float* vw   = (const float*)d_in[6];
    const float* vb   = (const float*)d_in[7];
    const float* ow   = (const float*)d_in[8];
    const float* ob   = (const float*)d_in[9];
    float* out = (float*)d_out;

    static int attr_done = 0;
    if (!attr_done) {
        cudaFuncSetAttribute(gemm_proj_kernel,  cudaFuncAttributeMaxDynamicSharedMemorySize, SMEM_BYTES);
        cudaFuncSetAttribute(gemm_hloc_kernel,  cudaFuncAttributeMaxDynamicSharedMemorySize, SMEM_BYTES);
        cudaFuncSetAttribute(gemm_qk_kernel,    cudaFuncAttributeMaxDynamicSharedMemorySize, SMEM_BYTES);
        cudaFuncSetAttribute(gemm_out_kernel,   cudaFuncAttributeMaxDynamicSharedMemorySize, SMEM_BYTES);
        cudaFuncSetAttribute(gemm_oproj_kernel, cudaFuncAttributeMaxDynamicSharedMemorySize, SMEM_BYTES);
        attr_done = 1;
    }

    conv_w_kernel<<<(int)(((size_t)4 * EE * EE + 255) / 256), 256>>>(qw, kw, vw, ow);
    conv_xT_kernel<<<dim3(TT / 32, EE / 32, BB), dim3(32, 8)>>>(x);

    gemm_proj_kernel<<<dim3(BB * TT / 128, EE / 128, 3), 256, SMEM_BYTES>>>(qb, kb, vb, toep);
    act_kernel<<<BB * TT, 128>>>();
    zprefix_kernel<<<(BB * EE + 127) / 128, 128>>>();

    gemm_hloc_kernel<<<dim3(EE / 128, EE / 128, BB * NCH), 256, SMEM_BYTES>>>();
    prefix_kernel<<<(int)(((size_t)BB * EE * EE + 255) / 256), 256>>>();

    gemm_qk_kernel<<<BB * NCH, 256, SMEM_BYTES>>>();
    dz_kernel<<<BB * NCH, 256>>>();
    gemm_out_kernel<<<dim3(EE / 128, BB * NCH), 256, SMEM_BYTES>>>();
    gemm_oproj_kernel<<<dim3(BB * TT / 128, EE / 128), 256, SMEM_BYTES>>>(ob, out);
}

// round 5
// speedup vs baseline: 2.7345x; 1.1495x over previous
#include <cuda_runtime.h>
#include <cuda_bf16.h>
#include <math.h>
#include <stdint.h>

#define BB 8
#define TT 2048
#define EE 512
#define CC 128
#define NCH 16
#define EPSV 1e-3f
#define INV_SQRT_E 0.04419417382415922f  // 512^-0.5

// ---------------------------------------------------------------------------
// scratch (device globals; no cudaMalloc allowed)
// ---------------------------------------------------------------------------
static __device__ float g_q[(size_t)BB * TT * EE];   // fp32 q (pre-softmax)

static __device__ __nv_bfloat16 xT_hi[(size_t)BB * TT * EE];
static __device__ __nv_bfloat16 xT_lo[(size_t)BB * TT * EE];
static __device__ __nv_bfloat16 w_hi[(size_t)4 * EE * EE];  // q,k,v,o
static __device__ __nv_bfloat16 w_lo[(size_t)4 * EE * EE];
static __device__ __nv_bfloat16 q_hi[(size_t)BB * TT * EE];
static __device__ __nv_bfloat16 q_lo[(size_t)BB * TT * EE];
static __device__ __nv_bfloat16 k_hi[(size_t)BB * TT * EE];
static __device__ __nv_bfloat16 k_lo[(size_t)BB * TT * EE];
static __device__ __nv_bfloat16 kT_hi[(size_t)BB * EE * TT];
static __device__ __nv_bfloat16 kT_lo[(size_t)BB * EE * TT];
static __device__ __nv_bfloat16 vT_hi[(size_t)BB * EE * TT];
static __device__ __nv_bfloat16 vT_lo[(size_t)BB * EE * TT];
static __device__ __nv_bfloat16 H_hi[(size_t)BB * NCH * EE * EE]; // local chunk states
static __device__ __nv_bfloat16 H_lo[(size_t)BB * NCH * EE * EE];
static __device__ __nv_bfloat16 S_hi[(size_t)BB * NCH * EE * EE]; // exclusive-prefix states
static __device__ __nv_bfloat16 S_lo[(size_t)BB * NCH * EE * EE];
static __device__ __nv_bfloat16 A_hi[(size_t)BB * NCH * CC * CC]; // masked QK^T
static __device__ __nv_bfloat16 A_lo[(size_t)BB * NCH * CC * CC];
static __device__ __nv_bfloat16 at_hi[(size_t)BB * TT * EE];      // attn output (split)
static __device__ __nv_bfloat16 at_lo[(size_t)BB * TT * EE];

static __device__ float g_z[(size_t)BB * NCH * EE];   // key colsums -> exclusive prefix
static __device__ float g_rs[(size_t)BB * NCH * CC];  // rowsum of masked A
static __device__ float g_dz[(size_t)BB * NCH * CC];  // q . z_excl

// ---------------------------------------------------------------------------
// helpers
// ---------------------------------------------------------------------------
__device__ __forceinline__ uint32_t smem_u32(const void* p) {
    uint32_t a;
    asm("{ .reg .u64 t; cvta.to.shared.u64 t, %1; cvt.u32.u64 %0, t; }" : "=r"(a) : "l"(p));
    return a;
}

__device__ __forceinline__ void ldm4(uint32_t* r, uint32_t addr) {
    asm volatile("ldmatrix.sync.aligned.m8n8.x4.shared.b16 {%0,%1,%2,%3}, [%4];"
                 : "=r"(r[0]), "=r"(r[1]), "=r"(r[2]), "=r"(r[3]) : "r"(addr));
}

__device__ __forceinline__ void mma16816(float* c, const uint32_t* a, uint32_t b0, uint32_t b1) {
    asm volatile(
        "mma.sync.aligned.m16n8k16.row.col.f32.bf16.bf16.f32 "
        "{%0,%1,%2,%3}, {%4,%5,%6,%7}, {%8,%9}, {%0,%1,%2,%3};"
        : "+f"(c[0]), "+f"(c[1]), "+f"(c[2]), "+f"(c[3])
        : "r"(a[0]), "r"(a[1]), "r"(a[2]), "r"(a[3]), "r"(b0), "r"(b1));
}

__device__ __forceinline__ void cpa16(uint32_t dst, const void* src) {
    asm volatile("cp.async.cg.shared.global [%0], [%1], 16;" :: "r"(dst), "l"(src));
}

__device__ __forceinline__ void split_pair(float x, float y, uint32_t& hi, uint32_t& lo) {
    __nv_bfloat16 hx = __float2bfloat16(x), hy = __float2bfloat16(y);
    __nv_bfloat16 lx = __float2bfloat16(x - __bfloat162float(hx));
    __nv_bfloat16 ly = __float2bfloat16(y - __bfloat162float(hy));
    hi = (uint32_t)__bfloat16_as_ushort(hx) | ((uint32_t)__bfloat16_as_ushort(hy) << 16);
    lo = (uint32_t)__bfloat16_as_ushort(lx) | ((uint32_t)__bfloat16_as_ushort(ly) << 16);
}

// ---------------------------------------------------------------------------
// block GEMM: C[m,n] += sum_k (Ahi+Alo)[m,k]*(Bhi+Blo)[n,k]
// block 128x128, BK=32, 3-stage cp.async pipeline, 256 threads,
// 8 warps (4 m x 2 n), warp tile 32x64.
// Stage layout (32KB): AHI 0 | ALO 8K | BHI 16K | BLO 24K.  64B rows, SW64-ish
// swizzle: chunk ^= (row>>1)&3  (conflict-free for stores and ldmatrix).
// ---------------------------------------------------------------------------
#define NSTAGE 3
#define STAGE_BYTES 32768
#define SMEM_BYTES (NSTAGE * STAGE_BYTES)

__device__ __forceinline__ void stage_load(
    uint32_t su, int buf,
    const __nv_bfloat16* __restrict__ ah, const __nv_bfloat16* __restrict__ al,
    const __nv_bfloat16* __restrict__ bh, const __nv_bfloat16* __restrict__ bl,
    int lda, int ldb, int kofs)
{
    uint32_t sb = su + (uint32_t)buf * STAGE_BYTES;
    int tid = threadIdx.x;
#pragma unroll
    for (int u = 0; u < 2; u++) {
        int ch = tid + u * 256;          // 0..511
        int row = ch >> 2, c16 = ch & 3; // 128 rows x 4 16B-chunks
        uint32_t so = (uint32_t)(row * 64 + ((c16 ^ ((row >> 1) & 3)) * 16));
        size_t goa = (size_t)row * lda + kofs + c16 * 8;
        size_t gob = (size_t)row * ldb + kofs + c16 * 8;
        cpa16(sb + so, ah + goa);
        cpa16(sb + 8192 + so, al + goa);
        cpa16(sb + 16384 + so, bh + gob);
        cpa16(sb + 24576 + so, bl + gob);
    }
    asm volatile("cp.async.commit_group;" ::: "memory");
}

__device__ __forceinline__ void gemm_block(
    float (&acc)[2][8][4], uint32_t su,
    const __nv_bfloat16* __restrict__ ah, const __nv_bfloat16* __restrict__ al,
    const __nv_bfloat16* __restrict__ bh, const __nv_bfloat16* __restrict__ bl,
    int lda, int ldb, int nk)
{
    __syncthreads();   // protect buffers from any prior use
    const int tid = threadIdx.x;
    const int lane = tid & 31, wid = tid >> 5;
    const int warp_m = wid >> 1, warp_n = wid & 1;
    const int q = lane >> 3, r8 = lane & 7;
    const int a_rowoff = warp_m * 32 + (q & 1) * 8 + r8;
    const int a_kcadd  = q >> 1;
    const int b_nbase  = warp_n * 64 + (q >> 1) * 8 + r8;
    const int b_kcadd  = q & 1;
    const int xor3a = (((q & 1) * 8 + r8) >> 1) & 3;
    const int xor3b = (((q >> 1) * 8 + r8) >> 1) & 3;

    // prologue: prefetch NSTAGE-1 stages
#pragma unroll
    for (int s = 0; s < NSTAGE - 1; s++) {
        if (s < nk) stage_load(su, s, ah, al, bh, bl, lda, ldb, s * 32);
        else asm volatile("cp.async.commit_group;" ::: "memory");
    }

    for (int kc = 0; kc < nk; kc++) {
        asm volatile("cp.async.wait_group %0;" :: "n"(NSTAGE - 2) : "memory");
        __syncthreads();
        int pf = kc + NSTAGE - 1;
        if (pf < nk) stage_load(su, pf % NSTAGE, ah, al, bh, bl, lda, ldb, pf * 32);
        else asm volatile("cp.async.commit_group;" ::: "memory");

        uint32_t sb = su + (uint32_t)(kc % NSTAGE) * STAGE_BYTES;
        uint32_t a_base = sb + (uint32_t)(a_rowoff * 64);
        uint32_t b_base = sb + 16384u + (uint32_t)(b_nbase * 64);
#pragma unroll
        for (int ks = 0; ks < 2; ks++) {
            uint32_t Ah[2][4], Al[2][4];
            uint32_t a_ch = (uint32_t)((((ks * 2 + a_kcadd) ^ xor3a) & 3) * 16);
#pragma unroll
            for (int mt = 0; mt < 2; mt++) {
                uint32_t addr = a_base + (uint32_t)(mt * 1024) + a_ch;
                ldm4(Ah[mt], addr);
                ldm4(Al[mt], addr + 8192u);
            }
            uint32_t b_ch = (uint32_t)((((ks * 2 + b_kcadd) ^ xor3b) & 3) * 16);
#pragma unroll
            for (int nt = 0; nt < 4; nt++) {
                uint32_t Bh[4], Bl[4];
                uint32_t baddr = b_base + (uint32_t)(nt * 1024) + b_ch;
                ldm4(Bh, baddr);
                ldm4(Bl, baddr + 8192u);
#pragma unroll
                for (int mt = 0; mt < 2; mt++) {
#pragma unroll
                    for (int h = 0; h < 2; h++) {
                        float* c = acc[mt][nt * 2 + h];
                        mma16816(c, Ah[mt], Bh[2 * h], Bh[2 * h + 1]);
                        mma16816(c, Ah[mt], Bl[2 * h], Bl[2 * h + 1]);
                        mma16816(c, Al[mt], Bh[2 * h], Bh[2 * h + 1]);
                    }
                }
            }
        }
    }
    __syncthreads();   // all warps done before smem reuse / next phase
}

#define ZERO_ACC(acc) do { \
    _Pragma("unroll") for (int _i = 0; _i < 2; _i++) \
    _Pragma("unroll") for (int _j = 0; _j < 8; _j++) \
    _Pragma("unroll") for (int _l = 0; _l < 4; _l++) acc[_i][_j][_l] = 0.f; \
} while (0)

#define EPI_VARS \
    const int tid = threadIdx.x; \
    const int lane = tid & 31, wid = tid >> 5; \
    const int warp_m = wid >> 1, warp_n = wid & 1; \
    const int g = lane >> 2, tg = lane & 3;

#define TPAD 136   // padded row length (elems) for transpose buffer (16B-mult)

// ---------------------------------------------------------------------------
// q/k/v projections: D[t,j] = sum_e xT[t,e] * W[j,e] + bias
//   which=0 (q): fp32 row-major -> g_q (softmax later in act)
//   which=1 (k): exp -> split row-major (k_hi/k_lo), transpose -> kT, colsum -> g_z
//   which=2 (v): *toep[t] -> transpose -> vT split only
// ---------------------------------------------------------------------------
__global__ __launch_bounds__(256, 2) void gemm_proj_kernel(
    const float* __restrict__ qb, const float* __restrict__ kb,
    const float* __restrict__ vb, const float* __restrict__ toep)
{
    extern __shared__ char sm[];
    __shared__ float zred[4][128];
    uint32_t su = smem_u32(sm);
    int m0 = blockIdx.x * 128, n0 = blockIdx.y * 128, which = blockIdx.z;

    float acc[2][8][4];
    ZERO_ACC(acc);
    gemm_block(acc, su,
               xT_hi + (size_t)m0 * EE, xT_lo + (size_t)m0 * EE,
               w_hi + (size_t)which * EE * EE + (size_t)n0 * EE,
               w_lo + (size_t)which * EE * EE + (size_t)n0 * EE,
               EE, EE, 16);

    EPI_VARS;
    const int b = m0 / TT, t0g = m0 % TT;
    __nv_bfloat16* buf = (__nv_bfloat16*)sm;   // reuse gemm smem for transpose

    if (which == 0) {
#pragma unroll
        for (int mt = 0; mt < 2; mt++)
#pragma unroll
            for (int h = 0; h < 2; h++) {
                int row = m0 + warp_m * 32 + mt * 16 + h * 8 + g;
#pragma unroll
                for (int nt = 0; nt < 8; nt++) {
                    int col = n0 + warp_n * 64 + nt * 8 + tg * 2;
                    float2 o;
                    o.x = acc[mt][nt][2 * h] + qb[col];
                    o.y = acc[mt][nt][2 * h + 1] + qb[col + 1];
                    *(float2*)&g_q[(size_t)row * EE + col] = o;
                }
            }
        return;
    }

    if (which == 1) {
        float cs[16];
#pragma unroll
        for (int i = 0; i < 16; i++) cs[i] = 0.f;
#pragma unroll
        for (int mt = 0; mt < 2; mt++)
#pragma unroll
            for (int h = 0; h < 2; h++) {
                int row = warp_m * 32 + mt * 16 + h * 8 + g;
#pragma unroll
                for (int nt = 0; nt < 8; nt++) {
                    int col = warp_n * 64 + nt * 8 + tg * 2;
                    float v0 = expf(acc[mt][nt][2 * h]     + kb[n0 + col]);
                    float v1 = expf(acc[mt][nt][2 * h + 1] + kb[n0 + col + 1]);
                    acc[mt][nt][2 * h] = v0;
                    acc[mt][nt][2 * h + 1] = v1;
                    cs[nt * 2] += v0;
                    cs[nt * 2 + 1] += v1;
                    uint32_t hi, lo;
                    split_pair(v0, v1, hi, lo);
                    *(uint32_t*)&k_hi[(size_t)(m0 + row) * EE + n0 + col] = hi;
                    *(uint32_t*)&k_lo[(size_t)(m0 + row) * EE + n0 + col] = lo;
                }
            }
#pragma unroll
        for (int i = 0; i < 16; i++) {
            cs[i] += __shfl_xor_sync(0xffffffffu, cs[i], 4);
            cs[i] += __shfl_xor_sync(0xffffffffu, cs[i], 8);
            cs[i] += __shfl_xor_sync(0xffffffffu, cs[i], 16);
        }
        if (g == 0) {
#pragma unroll
            for (int nt = 0; nt < 8; nt++) {
                int col = warp_n * 64 + nt * 8 + tg * 2;
                zred[warp_m][col] = cs[nt * 2];
                zred[warp_m][col + 1] = cs[nt * 2 + 1];
            }
        }
    } else {
#pragma unroll
        for (int mt = 0; mt < 2; mt++)
#pragma unroll
            for (int h = 0; h < 2; h++) {
                int row = warp_m * 32 + mt * 16 + h * 8 + g;
                float tw = toep[t0g + row];
#pragma unroll
                for (int nt = 0; nt < 8; nt++) {
                    int col = warp_n * 64 + nt * 8 + tg * 2;
                    acc[mt][nt][2 * h]     = (acc[mt][nt][2 * h]     + vb[n0 + col]) * tw;
                    acc[mt][nt][2 * h + 1] = (acc[mt][nt][2 * h + 1] + vb[n0 + col + 1]) * tw;
                }
            }
    }

    __nv_bfloat16* dsth = (which == 1) ? kT_hi : vT_hi;
    __nv_bfloat16* dstl = (which == 1) ? kT_lo : vT_lo;

    // pass 1: hi transpose
#pragma unroll
    for (int mt = 0; mt < 2; mt++)
#pragma unroll
        for (int h = 0; h < 2; h++) {
            int row = warp_m * 32 + mt * 16 + h * 8 + g;
#pragma unroll
            for (int nt = 0; nt < 8; nt++) {
                int col = warp_n * 64 + nt * 8 + tg * 2;
                buf[(size_t)col * TPAD + row] = __float2bfloat16(acc[mt][nt][2 * h]);
                buf[(size_t)(col + 1) * TPAD + row] = __float2bfloat16(acc[mt][nt][2 * h + 1]);
            }
        }
    __syncthreads();
    if (which == 1 && tid < 128) {
        int bc = b * NCH + t0g / CC;
        g_z[(size_t)bc * EE + n0 + tid] =
            zred[0][tid] + zred[1][tid] + zred[2][tid] + zred[3][tid];
    }
    {
        int e = tid >> 1, th = (tid & 1) * 64;
        const uint4* src = (const uint4*)(buf + (size_t)e * TPAD + th);
        uint4* dst = (uint4*)(dsth + ((size_t)b * EE + n0 + e) * TT + t0g + th);
#pragma unroll
        for (int i = 0; i < 8; i++) dst[i] = src[i];
    }
    __syncthreads();
    // pass 2: lo transpose
#pragma unroll
    for (int mt = 0; mt < 2; mt++)
#pragma unroll
        for (int h = 0; h < 2; h++) {
            int row = warp_m * 32 + mt * 16 + h * 8 + g;
#pragma unroll
            for (int nt = 0; nt < 8; nt++) {
                int col = warp_n * 64 + nt * 8 + tg * 2;
                float v0 = acc[mt][nt][2 * h], v1 = acc[mt][nt][2 * h + 1];
                buf[(size_t)col * TPAD + row] =
                    __float2bfloat16(v0 - __bfloat162float(__float2bfloat16(v0)));
                buf[(size_t)(col + 1) * TPAD + row] =
                    __float2bfloat16(v1 - __bfloat162float(__float2bfloat16(v1)));
            }
        }
    __syncthreads();
    {
        int e = tid >> 1, th = (tid & 1) * 64;
        const uint4* src = (const uint4*)(buf + (size_t)e * TPAD + th);
        uint4* dst = (uint4*)(dstl + ((size_t)b * EE + n0 + e) * TT + t0g + th);
#pragma unroll
        for (int i = 0; i < 8; i++) dst[i] = src[i];
    }
}

// ---------------------------------------------------------------------------
// chunk states: H'[e2,e1] = sum_t vT[e2,t] * kT[e1,t] -> split bf16 H
// ---------------------------------------------------------------------------
__global__ __launch_bounds__(256, 2) void gemm_hloc_kernel()
{
    extern __shared__ char sm[];
    uint32_t su = smem_u32(sm);
    int m0 = blockIdx.x * 128, n0 = blockIdx.y * 128;
    int bc = blockIdx.z, b = bc / NCH, c = bc % NCH;

    float acc[2][8][4];
    ZERO_ACC(acc);
    gemm_block(acc, su,
               vT_hi + ((size_t)b * EE + m0) * TT + (size_t)c * CC,
               vT_lo + ((size_t)b * EE + m0) * TT + (size_t)c * CC,
               kT_hi + ((size_t)b * EE + n0) * TT + (size_t)c * CC,
               kT_lo + ((size_t)b * EE + n0) * TT + (size_t)c * CC,
               TT, TT, 4);

    __nv_bfloat16* Hh = H_hi + (size_t)bc * EE * EE;
    __nv_bfloat16* Hl = H_lo + (size_t)bc * EE * EE;
    EPI_VARS;
    (void)tid; (void)lane;
#pragma unroll
    for (int mt = 0; mt < 2; mt++)
#pragma unroll
        for (int h = 0; h < 2; h++) {
            int row = m0 + warp_m * 32 + mt * 16 + h * 8 + g;
#pragma unroll
            for (int nt = 0; nt < 8; nt++) {
                int col = n0 + warp_n * 64 + nt * 8 + tg * 2;
                uint32_t hi, lo;
                split_pair(acc[mt][nt][2 * h], acc[mt][nt][2 * h + 1], hi, lo);
                *(uint32_t*)&Hh[(size_t)row * EE + col] = hi;
                *(uint32_t*)&Hl[(size_t)row * EE + col] = lo;
            }
        }
}

// ---------------------------------------------------------------------------
// A = causal-mask(Q K^T): rowsum -> g_rs, split bf16 -> A_hi/A_lo
// ---------------------------------------------------------------------------
__global__ __launch_bounds__(256, 2) void gemm_qk_kernel()
{
    extern __shared__ char sm[];
    __shared__ float s_rs[128][2];
    uint32_t su = smem_u32(sm);
    int bc = blockIdx.x, b = bc / NCH, c = bc % NCH;
    size_t base = ((size_t)b * TT + (size_t)c * CC) * EE;

    float acc[2][8][4];
    ZERO_ACC(acc);
    gemm_block(acc, su, q_hi + base, q_lo + base, k_hi + base, k_lo + base, EE, EE, 16);

    EPI_VARS;
    (void)lane;
    __nv_bfloat16* Ah = A_hi + (size_t)bc * CC * CC;
    __nv_bfloat16* Al = A_lo + (size_t)bc * CC * CC;
#pragma unroll
    for (int mt = 0; mt < 2; mt++)
#pragma unroll
        for (int h = 0; h < 2; h++) {
            int row = warp_m * 32 + mt * 16 + h * 8 + g;
            float rs = 0.f;
#pragma unroll
            for (int nt = 0; nt < 8; nt++) {
                int col = warp_n * 64 + nt * 8 + tg * 2;
                float v0 = acc[mt][nt][2 * h], v1 = acc[mt][nt][2 * h + 1];
                if (col > row) v0 = 0.f;
                if (col + 1 > row) v1 = 0.f;
                rs += v0 + v1;
                uint32_t hi, lo;
                split_pair(v0, v1, hi, lo);
                *(uint32_t*)&Ah[(size_t)row * CC + col] = hi;
                *(uint32_t*)&Al[(size_t)row * CC + col] = lo;
            }
            rs += __shfl_xor_sync(0xffffffffu, rs, 1);
            rs += __shfl_xor_sync(0xffffffffu, rs, 2);
            if (tg == 0) s_rs[row][warp_n] = rs;
        }
    __syncthreads();
    if (tid < 128)
        g_rs[(size_t)bc * CC + tid] = s_rs[tid][0] + s_rs[tid][1];
}

// ---------------------------------------------------------------------------
// out = (A @ V_c + Q @ S_c) / d, split -> at_hi/at_lo
// ---------------------------------------------------------------------------
__global__ __launch_bounds__(256, 2) void gemm_out_kernel()
{
    extern __shared__ char sm[];
    uint32_t su = smem_u32(sm);
    int n0 = blockIdx.x * 128;
    int bc = blockIdx.y, b = bc / NCH, c = bc % NCH;

    float acc[2][8][4];
    ZERO_ACC(acc);
    gemm_block(acc, su,
               A_hi + (size_t)bc * CC * CC, A_lo + (size_t)bc * CC * CC,
               vT_hi + ((size_t)b * EE + n0) * TT + (size_t)c * CC,
               vT_lo + ((size_t)b * EE + n0) * TT + (size_t)c * CC,
               CC, TT, 4);
    size_t qbase = ((size_t)b * TT + (size_t)c * CC) * EE;
    gemm_block(acc, su,
               q_hi + qbase, q_lo + qbase,
               S_hi + (size_t)bc * EE * EE + (size_t)n0 * EE,
               S_lo + (size_t)bc * EE * EE + (size_t)n0 * EE,
               EE, EE, 16);

    EPI_VARS;
    (void)tid; (void)lane;
#pragma unroll
    for (int mt = 0; mt < 2; mt++)
#pragma unroll
        for (int h = 0; h < 2; h++) {
            int row = warp_m * 32 + mt * 16 + h * 8 + g;
            float d = fmaxf(g_rs[(size_t)bc * CC + row] + g_dz[(size_t)bc * CC + row], EPSV);
            float inv = 1.0f / d;
            size_t ob = ((size_t)b * TT + (size_t)c * CC + row) * EE + n0;
#pragma unroll
            for (int nt = 0; nt < 8; nt++) {
                int col = warp_n * 64 + nt * 8 + tg * 2;
                uint32_t hi, lo;
                split_pair(acc[mt][nt][2 * h] * inv, acc[mt][nt][2 * h + 1] * inv, hi, lo);
                *(uint32_t*)&at_hi[ob + col] = hi;
                *(uint32_t*)&at_lo[ob + col] = lo;
            }
        }
}

// ---------------------------------------------------------------------------
// output projection -> d_out
// ---------------------------------------------------------------------------
__global__ __launch_bounds__(256, 2) void gemm_oproj_kernel(
    const float* __restrict__ ob_bias, float* __restrict__ outp)
{
    extern __shared__ char sm[];
    uint32_t su = smem_u32(sm);
    int m0 = blockIdx.x * 128, n0 = blockIdx.y * 128;

    float acc[2][8][4];
    ZERO_ACC(acc);
    gemm_block(acc, su,
               at_hi + (size_t)m0 * EE, at_lo + (size_t)m0 * EE,
               w_hi + (size_t)3 * EE * EE + (size_t)n0 * EE,
               w_lo + (size_t)3 * EE * EE + (size_t)n0 * EE,
               EE, EE, 16);

    EPI_VARS;
    (void)tid; (void)lane;
#pragma unroll
    for (int mt = 0; mt < 2; mt++)
#pragma unroll
        for (int h = 0; h < 2; h++) {
            int row = m0 + warp_m * 32 + mt * 16 + h * 8 + g;
#pragma unroll
            for (int nt = 0; nt < 8; nt++) {
                int col = n0 + warp_n * 64 + nt * 8 + tg * 2;
                float2 o;
                o.x = acc[mt][nt][2 * h] + ob_bias[col];
                o.y = acc[mt][nt][2 * h + 1] + ob_bias[col + 1];
                *(float2*)&outp[(size_t)row * EE + col] = o;
            }
        }
}

// ---------------------------------------------------------------------------
// conversion / elementwise kernels
// ---------------------------------------------------------------------------
__global__ __launch_bounds__(256) void conv_w_kernel(
    const float* __restrict__ qw, const float* __restrict__ kw,
    const float* __restrict__ vw, const float* __restrict__ ow)
{
    size_t idx = (size_t)blockIdx.x * 256 + threadIdx.x;
    if (idx >= (size_t)4 * EE * EE) return;
    int which = (int)(idx / ((size_t)EE * EE));
    size_t rem = idx % ((size_t)EE * EE);
    const float* w = (which == 0) ? qw : (which == 1) ? kw : (which == 2) ? vw : ow;
    float x = w[rem];
    __nv_bfloat16 h = __float2bfloat16(x);
    w_hi[idx] = h;
    w_lo[idx] = __float2bfloat16(x - __bfloat162float(h));
}

// x (B,E,T) fp32 -> xT (B,T,E) bf16 split
__global__ __launch_bounds__(256) void conv_xT_kernel(const float* __restrict__ x)
{
    __shared__ float ts[32][33];
    int b = blockIdx.z;
    int t0 = blockIdx.x * 32, e0 = blockIdx.y * 32;
    int tx = threadIdx.x, ty = threadIdx.y;  // (32,8)
    const float* xb = x + (size_t)b * EE * TT;
#pragma unroll
    for (int i = 0; i < 4; i++)
        ts[ty + i * 8][tx] = xb[(size_t)(e0 + ty + i * 8) * TT + t0 + tx];
    __syncthreads();
    size_t ob = (size_t)b * TT * EE;
#pragma unroll
    for (int i = 0; i < 4; i++) {
        float val = ts[tx][ty + i * 8];
        __nv_bfloat16 h = __float2bfloat16(val);
        size_t o = ob + (size_t)(t0 + ty + i * 8) * EE + e0 + tx;
        xT_hi[o] = h;
        xT_lo[o] = __float2bfloat16(val - __bfloat162float(h));
    }
}

// q softmax + split
__global__ __launch_bounds__(128) void act_kernel()
{
    int bt = blockIdx.x;
    int tid = threadIdx.x;
    size_t base = (size_t)bt * EE;
    __shared__ float sred[4];

    float qv[4];
#pragma unroll
    for (int u = 0; u < 4; u++) qv[u] = g_q[base + tid + u * 128];
    float m = fmaxf(fmaxf(qv[0], qv[1]), fmaxf(qv[2], qv[3]));
#pragma unroll
    for (int o = 16; o; o >>= 1) m = fmaxf(m, __shfl_xor_sync(0xffffffffu, m, o));
    if ((tid & 31) == 0) sred[tid >> 5] = m;
    __syncthreads();
    m = fmaxf(fmaxf(sred[0], sred[1]), fmaxf(sred[2], sred[3]));
    __syncthreads();
    float s = 0.f;
#pragma unroll
    for (int u = 0; u < 4; u++) { qv[u] = expf(qv[u] - m); s += qv[u]; }
#pragma unroll
    for (int o = 16; o; o >>= 1) s += __shfl_xor_sync(0xffffffffu, s, o);
    if ((tid & 31) == 0) sred[tid >> 5] = s;
    __syncthreads();
    s = sred[0] + sred[1] + sred[2] + sred[3];
    float scale = INV_SQRT_E / s;
#pragma unroll
    for (int u = 0; u < 4; u++) {
        size_t idx = base + tid + u * 128;
        float val = qv[u] * scale;
        __nv_bfloat16 h = __float2bfloat16(val);
        q_hi[idx] = h;
        q_lo[idx] = __float2bfloat16(val - __bfloat162float(h));
    }
}

__global__ __launch_bounds__(128) void zprefix_kernel()
{
    int idx = blockIdx.x * blockDim.x + threadIdx.x;
    if (idx >= BB * EE) return;
    int b = idx / EE, off = idx % EE;
    float run = 0.f;
    float* p = g_z + (size_t)b * NCH * EE + off;
#pragma unroll
    for (int c = 0; c < NCH; c++) {
        float tmp = *p; *p = run; run += tmp; p += EE;
    }
}

// exclusive prefix over chunks of split H -> split S
__global__ __launch_bounds__(256) void prefix_kernel()
{
    size_t idx = (size_t)blockIdx.x * 256 + threadIdx.x;
    const size_t nper = (size_t)EE * EE;
    if (idx >= (size_t)BB * nper) return;
    size_t b = idx / nper, off = idx % nper;
    float run = 0.f;
#pragma unroll
    for (int c = 0; c < NCH; c++) {
        size_t p = (b * NCH + c) * nper + off;
        float h = __bfloat162float(H_hi[p]) + __bfloat162float(H_lo[p]);
        __nv_bfloat16 rh = __float2bfloat16(run);
        S_hi[p] = rh;
        S_lo[p] = __float2bfloat16(run - __bfloat162float(rh));
        run += h;
    }
}

// dz[b,c,i] = sum_e q[b, c*128+i, e] * z_excl[b,c,e]   (q from split)
__global__ __launch_bounds__(256) void dz_kernel()
{
    int bc = blockIdx.x;
    int b = bc / NCH, c = bc % NCH;
    int w = threadIdx.x >> 5, lane = threadIdx.x & 31;
    const float* z = g_z + (size_t)bc * EE;
#pragma unroll
    for (int it = 0; it < 16; it++) {
        int i = it * 8 + w;
        size_t qrow = ((size_t)b * TT + (size_t)c * CC + i) * EE;
        float s = 0.f;
#pragma unroll 4
        for (int j = lane; j < EE; j += 32) {
            float qv = __bfloat162float(q_hi[qrow + j]) + __bfloat162float(q_lo[qrow + j]);
            s += qv * z[j];
        }
#pragma unroll
        for (int o = 16; o; o >>= 1) s += __shfl_xor_sync(0xffffffffu, s, o);
        if (lane == 0) g_dz[(size_t)bc * CC + i] = s;
    }
}

// ---------------------------------------------------------------------------
extern "C" void kernel_launch(void* const* d_in, const int* in_sizes, int n_in,
                              void* d_out, int out_size)
{
    const float* x    = (const float*)d_in[0];
    const float* toep = (const float*)d_in[1];
    const float* qw   = (const float*)d_in[2];
    const float* qb   = (const float*)d_in[3];
    const float* kw   = (const float*)d_in[4];
    const float* kb   = (const float*)d_in[5];
    const float* vw   = (const float*)d_in[6];
    const float* vb   = (const float*)d_in[7];
    const float* ow   = (const float*)d_in[8];
    const float* ob   = (const float*)d_in[9];
    float* out = (float*)d_out;

    static int attr_done = 0;
    if (!attr_done) {
        cudaFuncSetAttribute(gemm_proj_kernel,  cudaFuncAttributeMaxDynamicSharedMemorySize, SMEM_BYTES);
        cudaFuncSetAttribute(gemm_hloc_kernel,  cudaFuncAttributeMaxDynamicSharedMemorySize, SMEM_BYTES);
        cudaFuncSetAttribute(gemm_qk_kernel,    cudaFuncAttributeMaxDynamicSharedMemorySize, SMEM_BYTES);
        cudaFuncSetAttribute(gemm_out_kernel,   cudaFuncAttributeMaxDynamicSharedMemorySize, SMEM_BYTES);
        cudaFuncSetAttribute(gemm_oproj_kernel, cudaFuncAttributeMaxDynamicSharedMemorySize, SMEM_BYTES);
        attr_done = 1;
    }

    conv_w_kernel<<<(int)(((size_t)4 * EE * EE + 255) / 256), 256>>>(qw, kw, vw, ow);
    conv_xT_kernel<<<dim3(TT / 32, EE / 32, BB), dim3(32, 8)>>>(x);

    gemm_proj_kernel<<<dim3(BB * TT / 128, EE / 128, 3), 256, SMEM_BYTES>>>(qb, kb, vb, toep);
    act_kernel<<<BB * TT, 128>>>();
    zprefix_kernel<<<(BB * EE + 127) / 128, 128>>>();

    gemm_hloc_kernel<<<dim3(EE / 128, EE / 128, BB * NCH), 256, SMEM_BYTES>>>();
    prefix_kernel<<<(int)(((size_t)BB * EE * EE + 255) / 256), 256>>>();

    gemm_qk_kernel<<<BB * NCH, 256, SMEM_BYTES>>>();
    dz_kernel<<<BB * NCH, 256>>>();
    gemm_out_kernel<<<dim3(EE / 128, BB * NCH), 256, SMEM_BYTES>>>();
    gemm_oproj_kernel<<<dim3(BB * TT / 128, EE / 128), 256, SMEM_BYTES>>>(ob, out);
}

// round 6
// speedup vs baseline: 2.8047x; 1.0257x over previous
#include <cuda_runtime.h>
#include <cuda_bf16.h>
#include <math.h>
#include <stdint.h>

#define BB 8
#define TT 2048
#define EE 512
#define CC 128
#define NCH 16
#define EPSV 1e-3f
#define INV_SQRT_E 0.04419417382415922f  // 512^-0.5

// ---------------------------------------------------------------------------
// scratch (device globals; no cudaMalloc allowed)
// ---------------------------------------------------------------------------
static __device__ float g_q[(size_t)BB * TT * EE];   // fp32 q (pre-softmax)

static __device__ __nv_bfloat16 xT_hi[(size_t)BB * TT * EE];
static __device__ __nv_bfloat16 xT_lo[(size_t)BB * TT * EE];
static __device__ __nv_bfloat16 w_hi[(size_t)4 * EE * EE];  // q,k,v,o
static __device__ __nv_bfloat16 w_lo[(size_t)4 * EE * EE];
static __device__ __nv_bfloat16 q_hi[(size_t)BB * TT * EE];
static __device__ __nv_bfloat16 q_lo[(size_t)BB * TT * EE];
static __device__ __nv_bfloat16 k_hi[(size_t)BB * TT * EE];
static __device__ __nv_bfloat16 k_lo[(size_t)BB * TT * EE];
static __device__ __nv_bfloat16 kT_hi[(size_t)BB * EE * TT];
static __device__ __nv_bfloat16 kT_lo[(size_t)BB * EE * TT];
static __device__ __nv_bfloat16 vT_hi[(size_t)BB * EE * TT];
static __device__ __nv_bfloat16 vT_lo[(size_t)BB * EE * TT];
static __device__ __nv_bfloat16 H_hi[(size_t)BB * NCH * EE * EE]; // local chunk states
static __device__ __nv_bfloat16 H_lo[(size_t)BB * NCH * EE * EE];
static __device__ __nv_bfloat16 S_hi[(size_t)BB * NCH * EE * EE]; // exclusive-prefix states
static __device__ __nv_bfloat16 S_lo[(size_t)BB * NCH * EE * EE];
static __device__ __nv_bfloat16 A_hi[(size_t)BB * NCH * CC * CC]; // masked QK^T
static __device__ __nv_bfloat16 A_lo[(size_t)BB * NCH * CC * CC];
static __device__ __nv_bfloat16 at_hi[(size_t)BB * TT * EE];      // attn output (split)
static __device__ __nv_bfloat16 at_lo[(size_t)BB * TT * EE];

static __device__ float g_z[(size_t)BB * NCH * EE];   // key colsums -> exclusive prefix
static __device__ float g_rs[(size_t)BB * NCH * CC];  // rowsum of masked A
static __device__ float g_dz[(size_t)BB * NCH * CC];  // q . z_excl

// ---------------------------------------------------------------------------
// helpers
// ---------------------------------------------------------------------------
__device__ __forceinline__ uint32_t smem_u32(const void* p) {
    uint32_t a;
    asm("{ .reg .u64 t; cvta.to.shared.u64 t, %1; cvt.u32.u64 %0, t; }" : "=r"(a) : "l"(p));
    return a;
}

__device__ __forceinline__ void ldm4(uint32_t* r, uint32_t addr) {
    asm volatile("ldmatrix.sync.aligned.m8n8.x4.shared.b16 {%0,%1,%2,%3}, [%4];"
                 : "=r"(r[0]), "=r"(r[1]), "=r"(r[2]), "=r"(r[3]) : "r"(addr));
}

__device__ __forceinline__ void mma16816(float* c, const uint32_t* a, uint32_t b0, uint32_t b1) {
    asm volatile(
        "mma.sync.aligned.m16n8k16.row.col.f32.bf16.bf16.f32 "
        "{%0,%1,%2,%3}, {%4,%5,%6,%7}, {%8,%9}, {%0,%1,%2,%3};"
        : "+f"(c[0]), "+f"(c[1]), "+f"(c[2]), "+f"(c[3])
        : "r"(a[0]), "r"(a[1]), "r"(a[2]), "r"(a[3]), "r"(b0), "r"(b1));
}

__device__ __forceinline__ void cpa16(uint32_t dst, const void* src) {
    asm volatile("cp.async.cg.shared.global [%0], [%1], 16;" :: "r"(dst), "l"(src));
}

__device__ __forceinline__ void split_pair(float x, float y, uint32_t& hi, uint32_t& lo) {
    __nv_bfloat16 hx = __float2bfloat16(x), hy = __float2bfloat16(y);
    __nv_bfloat16 lx = __float2bfloat16(x - __bfloat162float(hx));
    __nv_bfloat16 ly = __float2bfloat16(y - __bfloat162float(hy));
    hi = (uint32_t)__bfloat16_as_ushort(hx) | ((uint32_t)__bfloat16_as_ushort(hy) << 16);
    lo = (uint32_t)__bfloat16_as_ushort(lx) | ((uint32_t)__bfloat16_as_ushort(ly) << 16);
}

// ---------------------------------------------------------------------------
// block GEMM: C[m,n] += sum_k (Ahi+Alo)[m,k]*(Bhi+Blo)[n,k]
// block 128x128, BK=32, 3-stage cp.async pipeline, 128 threads,
// 4 warps (2 m x 2 n), warp tile 64x64.
// Stage layout (32KB): AHI 0 | ALO 8K | BHI 16K | BLO 24K.  64B rows,
// swizzle: chunk ^= (row>>1)&3  (conflict-free for stores and ldmatrix).
// ---------------------------------------------------------------------------
#define NSTAGE 3
#define STAGE_BYTES 32768
#define SMEM_BYTES (NSTAGE * STAGE_BYTES)

__device__ __forceinline__ void stage_load(
    uint32_t su, int buf,
    const __nv_bfloat16* __restrict__ ah, const __nv_bfloat16* __restrict__ al,
    const __nv_bfloat16* __restrict__ bh, const __nv_bfloat16* __restrict__ bl,
    int lda, int ldb, int kofs)
{
    uint32_t sb = su + (uint32_t)buf * STAGE_BYTES;
    int tid = threadIdx.x;
#pragma unroll
    for (int u = 0; u < 4; u++) {
        int ch = tid + u * 128;          // 0..511
        int row = ch >> 2, c16 = ch & 3; // 128 rows x 4 16B-chunks
        uint32_t so = (uint32_t)(row * 64 + ((c16 ^ ((row >> 1) & 3)) * 16));
        size_t goa = (size_t)row * lda + kofs + c16 * 8;
        size_t gob = (size_t)row * ldb + kofs + c16 * 8;
        cpa16(sb + so, ah + goa);
        cpa16(sb + 8192 + so, al + goa);
        cpa16(sb + 16384 + so, bh + gob);
        cpa16(sb + 24576 + so, bl + gob);
    }
    asm volatile("cp.async.commit_group;" ::: "memory");
}

__device__ __forceinline__ void gemm_block(
    float (&acc)[4][8][4], uint32_t su,
    const __nv_bfloat16* __restrict__ ah, const __nv_bfloat16* __restrict__ al,
    const __nv_bfloat16* __restrict__ bh, const __nv_bfloat16* __restrict__ bl,
    int lda, int ldb, int nk)
{
    __syncthreads();   // protect buffers from any prior use
    const int tid = threadIdx.x;
    const int lane = tid & 31, wid = tid >> 5;      // 4 warps
    const int warp_m = wid >> 1, warp_n = wid & 1;
    const int q = lane >> 3, r8 = lane & 7;
    const int a_rowoff = warp_m * 64 + (q & 1) * 8 + r8;
    const int a_kcadd  = q >> 1;
    const int b_nbase  = warp_n * 64 + (q >> 1) * 8 + r8;
    const int b_kcadd  = q & 1;
    const int xor3a = (a_rowoff >> 1) & 3;
    const int xor3b = (b_nbase >> 1) & 3;

    // prologue: prefetch NSTAGE-1 stages
#pragma unroll
    for (int s = 0; s < NSTAGE - 1; s++) {
        if (s < nk) stage_load(su, s, ah, al, bh, bl, lda, ldb, s * 32);
        else asm volatile("cp.async.commit_group;" ::: "memory");
    }

    for (int kc = 0; kc < nk; kc++) {
        asm volatile("cp.async.wait_group %0;" :: "n"(NSTAGE - 2) : "memory");
        __syncthreads();
        int pf = kc + NSTAGE - 1;
        if (pf < nk) stage_load(su, pf % NSTAGE, ah, al, bh, bl, lda, ldb, pf * 32);
        else asm volatile("cp.async.commit_group;" ::: "memory");

        uint32_t sb = su + (uint32_t)(kc % NSTAGE) * STAGE_BYTES;
        uint32_t a_base = sb + (uint32_t)(a_rowoff * 64);
        uint32_t b_base = sb + 16384u + (uint32_t)(b_nbase * 64);
#pragma unroll
        for (int ks = 0; ks < 2; ks++) {
            uint32_t Ah[4][4], Al[4][4];
            uint32_t a_ch = (uint32_t)((((ks * 2 + a_kcadd) ^ xor3a) & 3) * 16);
#pragma unroll
            for (int mt = 0; mt < 4; mt++) {
                uint32_t addr = a_base + (uint32_t)(mt * 1024) + a_ch;
                ldm4(Ah[mt], addr);
                ldm4(Al[mt], addr + 8192u);
            }
            uint32_t b_ch = (uint32_t)((((ks * 2 + b_kcadd) ^ xor3b) & 3) * 16);
#pragma unroll
            for (int nt = 0; nt < 4; nt++) {
                uint32_t Bh[4], Bl[4];
                uint32_t baddr = b_base + (uint32_t)(nt * 1024) + b_ch;
                ldm4(Bh, baddr);
                ldm4(Bl, baddr + 8192u);
#pragma unroll
                for (int mt = 0; mt < 4; mt++) {
#pragma unroll
                    for (int h = 0; h < 2; h++) {
                        float* c = acc[mt][nt * 2 + h];
                        mma16816(c, Ah[mt], Bh[2 * h], Bh[2 * h + 1]);
                        mma16816(c, Ah[mt], Bl[2 * h], Bl[2 * h + 1]);
                        mma16816(c, Al[mt], Bh[2 * h], Bh[2 * h + 1]);
                    }
                }
            }
        }
    }
    __syncthreads();   // all warps done before smem reuse / next phase
}

#define ZERO_ACC(acc) do { \
    _Pragma("unroll") for (int _i = 0; _i < 4; _i++) \
    _Pragma("unroll") for (int _j = 0; _j < 8; _j++) \
    _Pragma("unroll") for (int _l = 0; _l < 4; _l++) acc[_i][_j][_l] = 0.f; \
} while (0)

// rows = warp_m*64 + mt*16 + h*8 + g; cols = warp_n*64 + nt*8 + tg*2
#define EPI_VARS \
    const int tid = threadIdx.x; \
    const int lane = tid & 31, wid = tid >> 5; \
    const int warp_m = wid >> 1, warp_n = wid & 1; \
    const int g = lane >> 2, tg = lane & 3;

#define TPAD 136   // padded row length (elems) for transpose buffer (16B-mult)

// ---------------------------------------------------------------------------
// q/k/v projections: D[t,j] = sum_e xT[t,e] * W[j,e] + bias
//   which=0 (q): fp32 row-major -> g_q (softmax later in act)
//   which=1 (k): exp -> split row-major (k_hi/k_lo), transpose -> kT, colsum -> g_z
//   which=2 (v): *toep[t] -> transpose -> vT split only
// ---------------------------------------------------------------------------
__global__ __launch_bounds__(128, 2) void gemm_proj_kernel(
    const float* __restrict__ qb, const float* __restrict__ kb,
    const float* __restrict__ vb, const float* __restrict__ toep)
{
    extern __shared__ char sm[];
    __shared__ float zred[2][128];
    uint32_t su = smem_u32(sm);
    int m0 = blockIdx.x * 128, n0 = blockIdx.y * 128, which = blockIdx.z;

    float acc[4][8][4];
    ZERO_ACC(acc);
    gemm_block(acc, su,
               xT_hi + (size_t)m0 * EE, xT_lo + (size_t)m0 * EE,
               w_hi + (size_t)which * EE * EE + (size_t)n0 * EE,
               w_lo + (size_t)which * EE * EE + (size_t)n0 * EE,
               EE, EE, 16);

    EPI_VARS;
    const int b = m0 / TT, t0g = m0 % TT;
    __nv_bfloat16* buf = (__nv_bfloat16*)sm;   // reuse gemm smem for transpose

    if (which == 0) {
#pragma unroll
        for (int mt = 0; mt < 4; mt++)
#pragma unroll
            for (int h = 0; h < 2; h++) {
                int row = m0 + warp_m * 64 + mt * 16 + h * 8 + g;
#pragma unroll
                for (int nt = 0; nt < 8; nt++) {
                    int col = n0 + warp_n * 64 + nt * 8 + tg * 2;
                    float2 o;
                    o.x = acc[mt][nt][2 * h] + qb[col];
                    o.y = acc[mt][nt][2 * h + 1] + qb[col + 1];
                    *(float2*)&g_q[(size_t)row * EE + col] = o;
                }
            }
        return;
    }

    if (which == 1) {
        float cs[16];
#pragma unroll
        for (int i = 0; i < 16; i++) cs[i] = 0.f;
#pragma unroll
        for (int mt = 0; mt < 4; mt++)
#pragma unroll
            for (int h = 0; h < 2; h++) {
                int row = warp_m * 64 + mt * 16 + h * 8 + g;
#pragma unroll
                for (int nt = 0; nt < 8; nt++) {
                    int col = warp_n * 64 + nt * 8 + tg * 2;
                    float v0 = expf(acc[mt][nt][2 * h]     + kb[n0 + col]);
                    float v1 = expf(acc[mt][nt][2 * h + 1] + kb[n0 + col + 1]);
                    acc[mt][nt][2 * h] = v0;
                    acc[mt][nt][2 * h + 1] = v1;
                    cs[nt * 2] += v0;
                    cs[nt * 2 + 1] += v1;
                    uint32_t hi, lo;
                    split_pair(v0, v1, hi, lo);
                    *(uint32_t*)&k_hi[(size_t)(m0 + row) * EE + n0 + col] = hi;
                    *(uint32_t*)&k_lo[(size_t)(m0 + row) * EE + n0 + col] = lo;
                }
            }
#pragma unroll
        for (int i = 0; i < 16; i++) {
            cs[i] += __shfl_xor_sync(0xffffffffu, cs[i], 4);
            cs[i] += __shfl_xor_sync(0xffffffffu, cs[i], 8);
            cs[i] += __shfl_xor_sync(0xffffffffu, cs[i], 16);
        }
        if (g == 0) {
#pragma unroll
            for (int nt = 0; nt < 8; nt++) {
                int col = warp_n * 64 + nt * 8 + tg * 2;
                zred[warp_m][col] = cs[nt * 2];
                zred[warp_m][col + 1] = cs[nt * 2 + 1];
            }
        }
    } else {
#pragma unroll
        for (int mt = 0; mt < 4; mt++)
#pragma unroll
            for (int h = 0; h < 2; h++) {
                int row = warp_m * 64 + mt * 16 + h * 8 + g;
                float tw = toep[t0g + row];
#pragma unroll
                for (int nt = 0; nt < 8; nt++) {
                    int col = warp_n * 64 + nt * 8 + tg * 2;
                    acc[mt][nt][2 * h]     = (acc[mt][nt][2 * h]     + vb[n0 + col]) * tw;
                    acc[mt][nt][2 * h + 1] = (acc[mt][nt][2 * h + 1] + vb[n0 + col + 1]) * tw;
                }
            }
    }

    __nv_bfloat16* dsth = (which == 1) ? kT_hi : vT_hi;
    __nv_bfloat16* dstl = (which == 1) ? kT_lo : vT_lo;

    // pass 1: hi transpose
#pragma unroll
    for (int mt = 0; mt < 4; mt++)
#pragma unroll
        for (int h = 0; h < 2; h++) {
            int row = warp_m * 64 + mt * 16 + h * 8 + g;
#pragma unroll
            for (int nt = 0; nt < 8; nt++) {
                int col = warp_n * 64 + nt * 8 + tg * 2;
                buf[(size_t)col * TPAD + row] = __float2bfloat16(acc[mt][nt][2 * h]);
                buf[(size_t)(col + 1) * TPAD + row] = __float2bfloat16(acc[mt][nt][2 * h + 1]);
            }
        }
    __syncthreads();
    if (which == 1) {
        int bc = b * NCH + t0g / CC;
        g_z[(size_t)bc * EE + n0 + tid] = zred[0][tid] + zred[1][tid];
    }
    {
        const uint4* src = (const uint4*)(buf + (size_t)tid * TPAD);
        uint4* dst = (uint4*)(dsth + ((size_t)b * EE + n0 + tid) * TT + t0g);
#pragma unroll
        for (int i = 0; i < 16; i++) dst[i] = src[i];
    }
    __syncthreads();
    // pass 2: lo transpose
#pragma unroll
    for (int mt = 0; mt < 4; mt++)
#pragma unroll
        for (int h = 0; h < 2; h++) {
            int row = warp_m * 64 + mt * 16 + h * 8 + g;
#pragma unroll
            for (int nt = 0; nt < 8; nt++) {
                int col = warp_n * 64 + nt * 8 + tg * 2;
                float v0 = acc[mt][nt][2 * h], v1 = acc[mt][nt][2 * h + 1];
                buf[(size_t)col * TPAD + row] =
                    __float2bfloat16(v0 - __bfloat162float(__float2bfloat16(v0)));
                buf[(size_t)(col + 1) * TPAD + row] =
                    __float2bfloat16(v1 - __bfloat162float(__float2bfloat16(v1)));
            }
        }
    __syncthreads();
    {
        const uint4* src = (const uint4*)(buf + (size_t)tid * TPAD);
        uint4* dst = (uint4*)(dstl + ((size_t)b * EE + n0 + tid) * TT + t0g);
#pragma unroll
        for (int i = 0; i < 16; i++) dst[i] = src[i];
    }
}

// ---------------------------------------------------------------------------
// chunk states: H'[e2,e1] = sum_t vT[e2,t] * kT[e1,t] -> split bf16 H
// ---------------------------------------------------------------------------
__global__ __launch_bounds__(128, 2) void gemm_hloc_kernel()
{
    extern __shared__ char sm[];
    uint32_t su = smem_u32(sm);
    int m0 = blockIdx.x * 128, n0 = blockIdx.y * 128;
    int bc = blockIdx.z, b = bc / NCH, c = bc % NCH;

    float acc[4][8][4];
    ZERO_ACC(acc);
    gemm_block(acc, su,
               vT_hi + ((size_t)b * EE + m0) * TT + (size_t)c * CC,
               vT_lo + ((size_t)b * EE + m0) * TT + (size_t)c * CC,
               kT_hi + ((size_t)b * EE + n0) * TT + (size_t)c * CC,
               kT_lo + ((size_t)b * EE + n0) * TT + (size_t)c * CC,
               TT, TT, 4);

    __nv_bfloat16* Hh = H_hi + (size_t)bc * EE * EE;
    __nv_bfloat16* Hl = H_lo + (size_t)bc * EE * EE;
    EPI_VARS;
    (void)tid; (void)lane;
#pragma unroll
    for (int mt = 0; mt < 4; mt++)
#pragma unroll
        for (int h = 0; h < 2; h++) {
            int row = m0 + warp_m * 64 + mt * 16 + h * 8 + g;
#pragma unroll
            for (int nt = 0; nt < 8; nt++) {
                int col = n0 + warp_n * 64 + nt * 8 + tg * 2;
                uint32_t hi, lo;
                split_pair(acc[mt][nt][2 * h], acc[mt][nt][2 * h + 1], hi, lo);
                *(uint32_t*)&Hh[(size_t)row * EE + col] = hi;
                *(uint32_t*)&Hl[(size_t)row * EE + col] = lo;
            }
        }
}

// ---------------------------------------------------------------------------
// A = causal-mask(Q K^T): rowsum -> g_rs, split bf16 -> A_hi/A_lo
// ---------------------------------------------------------------------------
__global__ __launch_bounds__(128, 2) void gemm_qk_kernel()
{
    extern __shared__ char sm[];
    __shared__ float s_rs[128][2];
    uint32_t su = smem_u32(sm);
    int bc = blockIdx.x, b = bc / NCH, c = bc % NCH;
    size_t base = ((size_t)b * TT + (size_t)c * CC) * EE;

    float acc[4][8][4];
    ZERO_ACC(acc);
    gemm_block(acc, su, q_hi + base, q_lo + base, k_hi + base, k_lo + base, EE, EE, 16);

    EPI_VARS;
    (void)lane;
    __nv_bfloat16* Ah = A_hi + (size_t)bc * CC * CC;
    __nv_bfloat16* Al = A_lo + (size_t)bc * CC * CC;
#pragma unroll
    for (int mt = 0; mt < 4; mt++)
#pragma unroll
        for (int h = 0; h < 2; h++) {
            int row = warp_m * 64 + mt * 16 + h * 8 + g;
            float rs = 0.f;
#pragma unroll
            for (int nt = 0; nt < 8; nt++) {
                int col = warp_n * 64 + nt * 8 + tg * 2;
                float v0 = acc[mt][nt][2 * h], v1 = acc[mt][nt][2 * h + 1];
                if (col > row) v0 = 0.f;
                if (col + 1 > row) v1 = 0.f;
                rs += v0 + v1;
                uint32_t hi, lo;
                split_pair(v0, v1, hi, lo);
                *(uint32_t*)&Ah[(size_t)row * CC + col] = hi;
                *(uint32_t*)&Al[(size_t)row * CC + col] = lo;
            }
            rs += __shfl_xor_sync(0xffffffffu, rs, 1);
            rs += __shfl_xor_sync(0xffffffffu, rs, 2);
            if (tg == 0) s_rs[row][warp_n] = rs;
        }
    __syncthreads();
    g_rs[(size_t)bc * CC + tid] = s_rs[tid][0] + s_rs[tid][1];
}

// ---------------------------------------------------------------------------
// out = (A @ V_c + Q @ S_c) / d, split -> at_hi/at_lo
// ---------------------------------------------------------------------------
__global__ __launch_bounds__(128, 2) void gemm_out_kernel()
{
    extern __shared__ char sm[];
    uint32_t su = smem_u32(sm);
    int n0 = blockIdx.x * 128;
    int bc = blockIdx.y, b = bc / NCH, c = bc % NCH;

    float acc[4][8][4];
    ZERO_ACC(acc);
    gemm_block(acc, su,
               A_hi + (size_t)bc * CC * CC, A_lo + (size_t)bc * CC * CC,
               vT_hi + ((size_t)b * EE + n0) * TT + (size_t)c * CC,
               vT_lo + ((size_t)b * EE + n0) * TT + (size_t)c * CC,
               CC, TT, 4);
    size_t qbase = ((size_t)b * TT + (size_t)c * CC) * EE;
    gemm_block(acc, su,
               q_hi + qbase, q_lo + qbase,
               S_hi + (size_t)bc * EE * EE + (size_t)n0 * EE,
               S_lo + (size_t)bc * EE * EE + (size_t)n0 * EE,
               EE, EE, 16);

    EPI_VARS;
    (void)tid; (void)lane;
#pragma unroll
    for (int mt = 0; mt < 4; mt++)
#pragma unroll
        for (int h = 0; h < 2; h++) {
            int row = warp_m * 64 + mt * 16 + h * 8 + g;
            float d = fmaxf(g_rs[(size_t)bc * CC + row] + g_dz[(size_t)bc * CC + row], EPSV);
            float inv = 1.0f / d;
            size_t ob = ((size_t)b * TT + (size_t)c * CC + row) * EE + n0;
#pragma unroll
            for (int nt = 0; nt < 8; nt++) {
                int col = warp_n * 64 + nt * 8 + tg * 2;
                uint32_t hi, lo;
                split_pair(acc[mt][nt][2 * h] * inv, acc[mt][nt][2 * h + 1] * inv, hi, lo);
                *(uint32_t*)&at_hi[ob + col] = hi;
                *(uint32_t*)&at_lo[ob + col] = lo;
            }
        }
}

// ---------------------------------------------------------------------------
// output projection -> d_out
// ---------------------------------------------------------------------------
__global__ __launch_bounds__(128, 2) void gemm_oproj_kernel(
    const float* __restrict__ ob_bias, float* __restrict__ outp)
{
    extern __shared__ char sm[];
    uint32_t su = smem_u32(sm);
    int m0 = blockIdx.x * 128, n0 = blockIdx.y * 128;

    float acc[4][8][4];
    ZERO_ACC(acc);
    gemm_block(acc, su,
               at_hi + (size_t)m0 * EE, at_lo + (size_t)m0 * EE,
               w_hi + (size_t)3 * EE * EE + (size_t)n0 * EE,
               w_lo + (size_t)3 * EE * EE + (size_t)n0 * EE,
               EE, EE, 16);

    EPI_VARS;
    (void)tid; (void)lane;
#pragma unroll
    for (int mt = 0; mt < 4; mt++)
#pragma unroll
        for (int h = 0; h < 2; h++) {
            int row = m0 + warp_m * 64 + mt * 16 + h * 8 + g;
#pragma unroll
            for (int nt = 0; nt < 8; nt++) {
                int col = n0 + warp_n * 64 + nt * 8 + tg * 2;
                float2 o;
                o.x = acc[mt][nt][2 * h] + ob_bias[col];
                o.y = acc[mt][nt][2 * h + 1] + ob_bias[col + 1];
                *(float2*)&outp[(size_t)row * EE + col] = o;
            }
        }
}

// ---------------------------------------------------------------------------
// conversion / elementwise kernels
// ---------------------------------------------------------------------------
__global__ __launch_bounds__(256) void conv_w_kernel(
    const float* __restrict__ qw, const float* __restrict__ kw,
    const float* __restrict__ vw, const float* __restrict__ ow)
{
    size_t idx = (size_t)blockIdx.x * 256 + threadIdx.x;
    if (idx >= (size_t)4 * EE * EE) return;
    int which = (int)(idx / ((size_t)EE * EE));
    size_t rem = idx % ((size_t)EE * EE);
    const float* w = (which == 0) ? qw : (which == 1) ? kw : (which == 2) ? vw : ow;
    float x = w[rem];
    __nv_bfloat16 h = __float2bfloat16(x);
    w_hi[idx] = h;
    w_lo[idx] = __float2bfloat16(x - __bfloat162float(h));
}

// x (B,E,T) fp32 -> xT (B,T,E) bf16 split
__global__ __launch_bounds__(256) void conv_xT_kernel(const float* __restrict__ x)
{
    __shared__ float ts[32][33];
    int b = blockIdx.z;
    int t0 = blockIdx.x * 32, e0 = blockIdx.y * 32;
    int tx = threadIdx.x, ty = threadIdx.y;  // (32,8)
    const float* xb = x + (size_t)b * EE * TT;
#pragma unroll
    for (int i = 0; i < 4; i++)
        ts[ty + i * 8][tx] = xb[(size_t)(e0 + ty + i * 8) * TT + t0 + tx];
    __syncthreads();
    size_t ob = (size_t)b * TT * EE;
#pragma unroll
    for (int i = 0; i < 4; i++) {
        float val = ts[tx][ty + i * 8];
        __nv_bfloat16 h = __float2bfloat16(val);
        size_t o = ob + (size_t)(t0 + ty + i * 8) * EE + e0 + tx;
        xT_hi[o] = h;
        xT_lo[o] = __float2bfloat16(val - __bfloat162float(h));
    }
}

// q softmax + split
__global__ __launch_bounds__(128) void act_kernel()
{
    int bt = blockIdx.x;
    int tid = threadIdx.x;
    size_t base = (size_t)bt * EE;
    __shared__ float sred[4];

    float qv[4];
#pragma unroll
    for (int u = 0; u < 4; u++) qv[u] = g_q[base + tid + u * 128];
    float m = fmaxf(fmaxf(qv[0], qv[1]), fmaxf(qv[2], qv[3]));
#pragma unroll
    for (int o = 16; o; o >>= 1) m = fmaxf(m, __shfl_xor_sync(0xffffffffu, m, o));
    if ((tid & 31) == 0) sred[tid >> 5] = m;
    __syncthreads();
    m = fmaxf(fmaxf(sred[0], sred[1]), fmaxf(sred[2], sred[3]));
    __syncthreads();
    float s = 0.f;
#pragma unroll
    for (int u = 0; u < 4; u++) { qv[u] = expf(qv[u] - m); s += qv[u]; }
#pragma unroll
    for (int o = 16; o; o >>= 1) s += __shfl_xor_sync(0xffffffffu, s, o);
    if ((tid & 31) == 0) sred[tid >> 5] = s;
    __syncthreads();
    s = sred[0] + sred[1] + sred[2] + sred[3];
    float scale = INV_SQRT_E / s;
#pragma unroll
    for (int u = 0; u < 4; u++) {
        size_t idx = base + tid + u * 128;
        float val = qv[u] * scale;
        __nv_bfloat16 h = __float2bfloat16(val);
        q_hi[idx] = h;
        q_lo[idx] = __float2bfloat16(val - __bfloat162float(h));
    }
}

__global__ __launch_bounds__(128) void zprefix_kernel()
{
    int idx = blockIdx.x * blockDim.x + threadIdx.x;
    if (idx >= BB * EE) return;
    int b = idx / EE, off = idx % EE;
    float run = 0.f;
    float* p = g_z + (size_t)b * NCH * EE + off;
#pragma unroll
    for (int c = 0; c < NCH; c++) {
        float tmp = *p; *p = run; run += tmp; p += EE;
    }
}

// exclusive prefix over chunks of split H -> split S
__global__ __launch_bounds__(256) void prefix_kernel()
{
    size_t idx = (size_t)blockIdx.x * 256 + threadIdx.x;
    const size_t nper = (size_t)EE * EE;
    if (idx >= (size_t)BB * nper) return;
    size_t b = idx / nper, off = idx % nper;
    float run = 0.f;
#pragma unroll
    for (int c = 0; c < NCH; c++) {
        size_t p = (b * NCH + c) * nper + off;
        float h = __bfloat162float(H_hi[p]) + __bfloat162float(H_lo[p]);
        __nv_bfloat16 rh = __float2bfloat16(run);
        S_hi[p] = rh;
        S_lo[p] = __float2bfloat16(run - __bfloat162float(rh));
        run += h;
    }
}

// dz[b,c,i] = sum_e q[b, c*128+i, e] * z_excl[b,c,e]   (q from split)
__global__ __launch_bounds__(256) void dz_kernel()
{
    int bc = blockIdx.x;
    int b = bc / NCH, c = bc % NCH;
    int w = threadIdx.x >> 5, lane = threadIdx.x & 31;
    const float* z = g_z + (size_t)bc * EE;
#pragma unroll
    for (int it = 0; it < 16; it++) {
        int i = it * 8 + w;
        size_t qrow = ((size_t)b * TT + (size_t)c * CC + i) * EE;
        float s = 0.f;
#pragma unroll 4
        for (int j = lane; j < EE; j += 32) {
            float qv = __bfloat162float(q_hi[qrow + j]) + __bfloat162float(q_lo[qrow + j]);
            s += qv * z[j];
        }
#pragma unroll
        for (int o = 16; o; o >>= 1) s += __shfl_xor_sync(0xffffffffu, s, o);
        if (lane == 0) g_dz[(size_t)bc * CC + i] = s;
    }
}

// ---------------------------------------------------------------------------
extern "C" void kernel_launch(void* const* d_in, const int* in_sizes, int n_in,
                              void* d_out, int out_size)
{
    const float* x    = (const float*)d_in[0];
    const float* toep = (const float*)d_in[1];
    const float* qw   = (const float*)d_in[2];
    const float* qb   = (const float*)d_in[3];
    const float* kw   = (const float*)d_in[4];
    const float* kb   = (const float*)d_in[5];
    const float* vw   = (const float*)d_in[6];
    const float* vb   = (const float*)d_in[7];
    const float* ow   = (const float*)d_in[8];
    const float* ob   = (const float*)d_in[9];
    float* out = (float*)d_out;

    static int attr_done = 0;
    if (!attr_done) {
        cudaFuncSetAttribute(gemm_proj_kernel,  cudaFuncAttributeMaxDynamicSharedMemorySize, SMEM_BYTES);
        cudaFuncSetAttribute(gemm_hloc_kernel,  cudaFuncAttributeMaxDynamicSharedMemorySize, SMEM_BYTES);
        cudaFuncSetAttribute(gemm_qk_kernel,    cudaFuncAttributeMaxDynamicSharedMemorySize, SMEM_BYTES);
        cudaFuncSetAttribute(gemm_out_kernel,   cudaFuncAttributeMaxDynamicSharedMemorySize, SMEM_BYTES);
        cudaFuncSetAttribute(gemm_oproj_kernel, cudaFuncAttributeMaxDynamicSharedMemorySize, SMEM_BYTES);
        attr_done = 1;
    }

    conv_w_kernel<<<(int)(((size_t)4 * EE * EE + 255) / 256), 256>>>(qw, kw, vw, ow);
    conv_xT_kernel<<<dim3(TT / 32, EE / 32, BB), dim3(32, 8)>>>(x);

    gemm_proj_kernel<<<dim3(BB * TT / 128, EE / 128, 3), 128, SMEM_BYTES>>>(qb, kb, vb, toep);
    act_kernel<<<BB * TT, 128>>>();
    zprefix_kernel<<<(BB * EE + 127) / 128, 128>>>();

    gemm_hloc_kernel<<<dim3(EE / 128, EE / 128, BB * NCH), 128, SMEM_BYTES>>>();
    prefix_kernel<<<(int)(((size_t)BB * EE * EE + 255) / 256), 256>>>();

    gemm_qk_kernel<<<BB * NCH, 128, SMEM_BYTES>>>();
    dz_kernel<<<BB * NCH, 256>>>();
    gemm_out_kernel<<<dim3(EE / 128, BB * NCH), 128, SMEM_BYTES>>>();
    gemm_oproj_kernel<<<dim3(BB * TT / 128, EE / 128), 128, SMEM_BYTES>>>(ob, out);
}

// round 7
// speedup vs baseline: 3.0974x; 1.1044x over previous
#include <cuda_runtime.h>
#include <cuda_bf16.h>
#include <math.h>
#include <stdint.h>

#define BB 8
#define TT 2048
#define EE 512
#define CC 128
#define NCH 16
#define EPSV 1e-3f
#define INV_SQRT_E 0.04419417382415922f  // 512^-0.5

// ---------------------------------------------------------------------------
// scratch (device globals; no cudaMalloc allowed)
// ---------------------------------------------------------------------------
static __device__ float g_q[(size_t)BB * TT * EE];   // fp32 q (pre-softmax)

static __device__ __nv_bfloat16 xT_hi[(size_t)BB * TT * EE];
static __device__ __nv_bfloat16 xT_lo[(size_t)BB * TT * EE];
static __device__ __nv_bfloat16 w_hi[(size_t)4 * EE * EE];  // q,k,v,o
static __device__ __nv_bfloat16 w_lo[(size_t)4 * EE * EE];
static __device__ __nv_bfloat16 q_hi[(size_t)BB * TT * EE];
static __device__ __nv_bfloat16 q_lo[(size_t)BB * TT * EE];
static __device__ __nv_bfloat16 k_hi[(size_t)BB * TT * EE];
static __device__ __nv_bfloat16 k_lo[(size_t)BB * TT * EE];
static __device__ __nv_bfloat16 kT_hi[(size_t)BB * EE * TT];
static __device__ __nv_bfloat16 kT_lo[(size_t)BB * EE * TT];
static __device__ __nv_bfloat16 vT_hi[(size_t)BB * EE * TT];
static __device__ __nv_bfloat16 vT_lo[(size_t)BB * EE * TT];
static __device__ __nv_bfloat16 S_hi[(size_t)BB * NCH * EE * EE]; // exclusive-prefix states
static __device__ __nv_bfloat16 S_lo[(size_t)BB * NCH * EE * EE];
static __device__ __nv_bfloat16 A_hi[(size_t)BB * NCH * CC * CC]; // masked QK^T
static __device__ __nv_bfloat16 A_lo[(size_t)BB * NCH * CC * CC];
static __device__ __nv_bfloat16 at_hi[(size_t)BB * TT * EE];      // attn output (split)
static __device__ __nv_bfloat16 at_lo[(size_t)BB * TT * EE];

static __device__ float g_z[(size_t)BB * NCH * EE];   // key colsums -> exclusive prefix
static __device__ float g_rs[(size_t)BB * NCH * CC];  // rowsum of masked A
static __device__ float g_dz[(size_t)BB * NCH * CC];  // q . z_excl

// ---------------------------------------------------------------------------
// helpers
// ---------------------------------------------------------------------------
__device__ __forceinline__ uint32_t smem_u32(const void* p) {
    uint32_t a;
    asm("{ .reg .u64 t; cvta.to.shared.u64 t, %1; cvt.u32.u64 %0, t; }" : "=r"(a) : "l"(p));
    return a;
}

__device__ __forceinline__ void ldm4(uint32_t* r, uint32_t addr) {
    asm volatile("ldmatrix.sync.aligned.m8n8.x4.shared.b16 {%0,%1,%2,%3}, [%4];"
                 : "=r"(r[0]), "=r"(r[1]), "=r"(r[2]), "=r"(r[3]) : "r"(addr));
}

__device__ __forceinline__ void mma16816(float* c, const uint32_t* a, uint32_t b0, uint32_t b1) {
    asm volatile(
        "mma.sync.aligned.m16n8k16.row.col.f32.bf16.bf16.f32 "
        "{%0,%1,%2,%3}, {%4,%5,%6,%7}, {%8,%9}, {%0,%1,%2,%3};"
        : "+f"(c[0]), "+f"(c[1]), "+f"(c[2]), "+f"(c[3])
        : "r"(a[0]), "r"(a[1]), "r"(a[2]), "r"(a[3]), "r"(b0), "r"(b1));
}

__device__ __forceinline__ void cpa16(uint32_t dst, const void* src) {
    asm volatile("cp.async.cg.shared.global [%0], [%1], 16;" :: "r"(dst), "l"(src));
}

__device__ __forceinline__ void split_pair(float x, float y, uint32_t& hi, uint32_t& lo) {
    __nv_bfloat16 hx = __float2bfloat16(x), hy = __float2bfloat16(y);
    __nv_bfloat16 lx = __float2bfloat16(x - __bfloat162float(hx));
    __nv_bfloat16 ly = __float2bfloat16(y - __bfloat162float(hy));
    hi = (uint32_t)__bfloat16_as_ushort(hx) | ((uint32_t)__bfloat16_as_ushort(hy) << 16);
    lo = (uint32_t)__bfloat16_as_ushort(lx) | ((uint32_t)__bfloat16_as_ushort(ly) << 16);
}

// ---------------------------------------------------------------------------
// block GEMM: C[m,n] += sum_k (Ahi+Alo)[m,k]*(Bhi+Blo)[n,k]
// block 128x128, BK=32, 3-stage cp.async pipeline, 128 threads,
// 4 warps (2 m x 2 n), warp tile 64x64.
// Stage layout (32KB): AHI 0 | ALO 8K | BHI 16K | BLO 24K.  64B rows,
// swizzle: chunk ^= (row>>1)&3  (conflict-free for stores and ldmatrix).
// ---------------------------------------------------------------------------
#define NSTAGE 3
#define STAGE_BYTES 32768
#define SMEM_BYTES (NSTAGE * STAGE_BYTES)

__device__ __forceinline__ void stage_load(
    uint32_t su, int buf,
    const __nv_bfloat16* __restrict__ ah, const __nv_bfloat16* __restrict__ al,
    const __nv_bfloat16* __restrict__ bh, const __nv_bfloat16* __restrict__ bl,
    int lda, int ldb, int kofs)
{
    uint32_t sb = su + (uint32_t)buf * STAGE_BYTES;
    int tid = threadIdx.x;
#pragma unroll
    for (int u = 0; u < 4; u++) {
        int ch = tid + u * 128;          // 0..511
        int row = ch >> 2, c16 = ch & 3; // 128 rows x 4 16B-chunks
        uint32_t so = (uint32_t)(row * 64 + ((c16 ^ ((row >> 1) & 3)) * 16));
        size_t goa = (size_t)row * lda + kofs + c16 * 8;
        size_t gob = (size_t)row * ldb + kofs + c16 * 8;
        cpa16(sb + so, ah + goa);
        cpa16(sb + 8192 + so, al + goa);
        cpa16(sb + 16384 + so, bh + gob);
        cpa16(sb + 24576 + so, bl + gob);
    }
    asm volatile("cp.async.commit_group;" ::: "memory");
}

__device__ __forceinline__ void gemm_block(
    float (&acc)[4][8][4], uint32_t su,
    const __nv_bfloat16* __restrict__ ah, const __nv_bfloat16* __restrict__ al,
    const __nv_bfloat16* __restrict__ bh, const __nv_bfloat16* __restrict__ bl,
    int lda, int ldb, int nk)
{
    __syncthreads();   // protect buffers from any prior use
    const int tid = threadIdx.x;
    const int lane = tid & 31, wid = tid >> 5;      // 4 warps
    const int warp_m = wid >> 1, warp_n = wid & 1;
    const int q = lane >> 3, r8 = lane & 7;
    const int a_rowoff = warp_m * 64 + (q & 1) * 8 + r8;
    const int a_kcadd  = q >> 1;
    const int b_nbase  = warp_n * 64 + (q >> 1) * 8 + r8;
    const int b_kcadd  = q & 1;
    const int xor3a = (a_rowoff >> 1) & 3;
    const int xor3b = (b_nbase >> 1) & 3;

    // prologue: prefetch NSTAGE-1 stages
#pragma unroll
    for (int s = 0; s < NSTAGE - 1; s++) {
        if (s < nk) stage_load(su, s, ah, al, bh, bl, lda, ldb, s * 32);
        else asm volatile("cp.async.commit_group;" ::: "memory");
    }

    for (int kc = 0; kc < nk; kc++) {
        asm volatile("cp.async.wait_group %0;" :: "n"(NSTAGE - 2) : "memory");
        __syncthreads();
        int pf = kc + NSTAGE - 1;
        if (pf < nk) stage_load(su, pf % NSTAGE, ah, al, bh, bl, lda, ldb, pf * 32);
        else asm volatile("cp.async.commit_group;" ::: "memory");

        uint32_t sb = su + (uint32_t)(kc % NSTAGE) * STAGE_BYTES;
        uint32_t a_base = sb + (uint32_t)(a_rowoff * 64);
        uint32_t b_base = sb + 16384u + (uint32_t)(b_nbase * 64);
#pragma unroll
        for (int ks = 0; ks < 2; ks++) {
            uint32_t Ah[4][4], Al[4][4];
            uint32_t a_ch = (uint32_t)((((ks * 2 + a_kcadd) ^ xor3a) & 3) * 16);
#pragma unroll
            for (int mt = 0; mt < 4; mt++) {
                uint32_t addr = a_base + (uint32_t)(mt * 1024) + a_ch;
                ldm4(Ah[mt], addr);
                ldm4(Al[mt], addr + 8192u);
            }
            uint32_t b_ch = (uint32_t)((((ks * 2 + b_kcadd) ^ xor3b) & 3) * 16);
#pragma unroll
            for (int nt = 0; nt < 4; nt++) {
                uint32_t Bh[4], Bl[4];
                uint32_t baddr = b_base + (uint32_t)(nt * 1024) + b_ch;
                ldm4(Bh, baddr);
                ldm4(Bl, baddr + 8192u);
#pragma unroll
                for (int mt = 0; mt < 4; mt++) {
#pragma unroll
                    for (int h = 0; h < 2; h++) {
                        float* c = acc[mt][nt * 2 + h];
                        mma16816(c, Ah[mt], Bh[2 * h], Bh[2 * h + 1]);
                        mma16816(c, Ah[mt], Bl[2 * h], Bl[2 * h + 1]);
                        mma16816(c, Al[mt], Bh[2 * h], Bh[2 * h + 1]);
                    }
                }
            }
        }
    }
    __syncthreads();   // all warps done before smem reuse / next phase
}

#define ZERO_ACC(acc) do { \
    _Pragma("unroll") for (int _i = 0; _i < 4; _i++) \
    _Pragma("unroll") for (int _j = 0; _j < 8; _j++) \
    _Pragma("unroll") for (int _l = 0; _l < 4; _l++) acc[_i][_j][_l] = 0.f; \
} while (0)

// rows = warp_m*64 + mt*16 + h*8 + g; cols = warp_n*64 + nt*8 + tg*2
#define EPI_VARS \
    const int tid = threadIdx.x; \
    const int lane = tid & 31, wid = tid >> 5; \
    const int warp_m = wid >> 1, warp_n = wid & 1; \
    const int g = lane >> 2, tg = lane & 3;

#define TPAD 136   // padded row length (elems) for transpose buffer (16B-mult)

// ---------------------------------------------------------------------------
// q/k/v projections: D[t,j] = sum_e xT[t,e] * W[j,e] + bias
//   which=0 (q): fp32 row-major -> g_q (softmax later in act)
//   which=1 (k): exp -> split row-major (k_hi/k_lo), transpose -> kT, colsum -> g_z
//   which=2 (v): *toep[t] -> transpose -> vT split only
// ---------------------------------------------------------------------------
__global__ __launch_bounds__(128, 2) void gemm_proj_kernel(
    const float* __restrict__ qb, const float* __restrict__ kb,
    const float* __restrict__ vb, const float* __restrict__ toep)
{
    extern __shared__ char sm[];
    __shared__ float zred[2][128];
    uint32_t su = smem_u32(sm);
    int m0 = blockIdx.x * 128, n0 = blockIdx.y * 128, which = blockIdx.z;

    float acc[4][8][4];
    ZERO_ACC(acc);
    gemm_block(acc, su,
               xT_hi + (size_t)m0 * EE, xT_lo + (size_t)m0 * EE,
               w_hi + (size_t)which * EE * EE + (size_t)n0 * EE,
               w_lo + (size_t)which * EE * EE + (size_t)n0 * EE,
               EE, EE, 16);

    EPI_VARS;
    const int b = m0 / TT, t0g = m0 % TT;
    __nv_bfloat16* buf = (__nv_bfloat16*)sm;   // reuse gemm smem for transpose

    if (which == 0) {
#pragma unroll
        for (int mt = 0; mt < 4; mt++)
#pragma unroll
            for (int h = 0; h < 2; h++) {
                int row = m0 + warp_m * 64 + mt * 16 + h * 8 + g;
#pragma unroll
                for (int nt = 0; nt < 8; nt++) {
                    int col = n0 + warp_n * 64 + nt * 8 + tg * 2;
                    float2 o;
                    o.x = acc[mt][nt][2 * h] + qb[col];
                    o.y = acc[mt][nt][2 * h + 1] + qb[col + 1];
                    *(float2*)&g_q[(size_t)row * EE + col] = o;
                }
            }
        return;
    }

    if (which == 1) {
        float cs[16];
#pragma unroll
        for (int i = 0; i < 16; i++) cs[i] = 0.f;
#pragma unroll
        for (int mt = 0; mt < 4; mt++)
#pragma unroll
            for (int h = 0; h < 2; h++) {
                int row = warp_m * 64 + mt * 16 + h * 8 + g;
#pragma unroll
                for (int nt = 0; nt < 8; nt++) {
                    int col = warp_n * 64 + nt * 8 + tg * 2;
                    float v0 = expf(acc[mt][nt][2 * h]     + kb[n0 + col]);
                    float v1 = expf(acc[mt][nt][2 * h + 1] + kb[n0 + col + 1]);
                    acc[mt][nt][2 * h] = v0;
                    acc[mt][nt][2 * h + 1] = v1;
                    cs[nt * 2] += v0;
                    cs[nt * 2 + 1] += v1;
                    uint32_t hi, lo;
                    split_pair(v0, v1, hi, lo);
                    *(uint32_t*)&k_hi[(size_t)(m0 + row) * EE + n0 + col] = hi;
                    *(uint32_t*)&k_lo[(size_t)(m0 + row) * EE + n0 + col] = lo;
                }
            }
#pragma unroll
        for (int i = 0; i < 16; i++) {
            cs[i] += __shfl_xor_sync(0xffffffffu, cs[i], 4);
            cs[i] += __shfl_xor_sync(0xffffffffu, cs[i], 8);
            cs[i] += __shfl_xor_sync(0xffffffffu, cs[i], 16);
        }
        if (g == 0) {
#pragma unroll
            for (int nt = 0; nt < 8; nt++) {
                int col = warp_n * 64 + nt * 8 + tg * 2;
                zred[warp_m][col] = cs[nt * 2];
                zred[warp_m][col + 1] = cs[nt * 2 + 1];
            }
        }
    } else {
#pragma unroll
        for (int mt = 0; mt < 4; mt++)
#pragma unroll
            for (int h = 0; h < 2; h++) {
                int row = warp_m * 64 + mt * 16 + h * 8 + g;
                float tw = toep[t0g + row];
#pragma unroll
                for (int nt = 0; nt < 8; nt++) {
                    int col = warp_n * 64 + nt * 8 + tg * 2;
                    acc[mt][nt][2 * h]     = (acc[mt][nt][2 * h]     + vb[n0 + col]) * tw;
                    acc[mt][nt][2 * h + 1] = (acc[mt][nt][2 * h + 1] + vb[n0 + col + 1]) * tw;
                }
            }
    }

    __nv_bfloat16* dsth = (which == 1) ? kT_hi : vT_hi;
    __nv_bfloat16* dstl = (which == 1) ? kT_lo : vT_lo;

    // pass 1: hi transpose
#pragma unroll
    for (int mt = 0; mt < 4; mt++)
#pragma unroll
        for (int h = 0; h < 2; h++) {
            int row = warp_m * 64 + mt * 16 + h * 8 + g;
#pragma unroll
            for (int nt = 0; nt < 8; nt++) {
                int col = warp_n * 64 + nt * 8 + tg * 2;
                buf[(size_t)col * TPAD + row] = __float2bfloat16(acc[mt][nt][2 * h]);
                buf[(size_t)(col + 1) * TPAD + row] = __float2bfloat16(acc[mt][nt][2 * h + 1]);
            }
        }
    __syncthreads();
    if (which == 1) {
        int bc = b * NCH + t0g / CC;
        g_z[(size_t)bc * EE + n0 + tid] = zred[0][tid] + zred[1][tid];
    }
    {
        const uint4* src = (const uint4*)(buf + (size_t)tid * TPAD);
        uint4* dst = (uint4*)(dsth + ((size_t)b * EE + n0 + tid) * TT + t0g);
#pragma unroll
        for (int i = 0; i < 16; i++) dst[i] = src[i];
    }
    __syncthreads();
    // pass 2: lo transpose
#pragma unroll
    for (int mt = 0; mt < 4; mt++)
#pragma unroll
        for (int h = 0; h < 2; h++) {
            int row = warp_m * 64 + mt * 16 + h * 8 + g;
#pragma unroll
            for (int nt = 0; nt < 8; nt++) {
                int col = warp_n * 64 + nt * 8 + tg * 2;
                float v0 = acc[mt][nt][2 * h], v1 = acc[mt][nt][2 * h + 1];
                buf[(size_t)col * TPAD + row] =
                    __float2bfloat16(v0 - __bfloat162float(__float2bfloat16(v0)));
                buf[(size_t)(col + 1) * TPAD + row] =
                    __float2bfloat16(v1 - __bfloat162float(__float2bfloat16(v1)));
            }
        }
    __syncthreads();
    {
        const uint4* src = (const uint4*)(buf + (size_t)tid * TPAD);
        uint4* dst = (uint4*)(dstl + ((size_t)b * EE + n0 + tid) * TT + t0g);
#pragma unroll
        for (int i = 0; i < 16; i++) dst[i] = src[i];
    }
}

// ---------------------------------------------------------------------------
// fused chunk-state scan: per (m0, n0, b), walk chunks c = 0..15;
// write S_c = running fp32 acc (split), then acc += K_c^T V_c piece.
// Replaces hloc + prefix: H tensor never touches DRAM.
// ---------------------------------------------------------------------------
__global__ __launch_bounds__(128, 2) void gemm_hscan_kernel()
{
    extern __shared__ char sm[];
    uint32_t su = smem_u32(sm);
    int m0 = blockIdx.x * 128, n0 = blockIdx.y * 128;
    int b = blockIdx.z;

    float acc[4][8][4];
    ZERO_ACC(acc);
    EPI_VARS;
    (void)tid; (void)lane;

    for (int c = 0; c < NCH; c++) {
        int bc = b * NCH + c;
        // write exclusive-prefix state S_c = acc
        __nv_bfloat16* Sh = S_hi + (size_t)bc * EE * EE;
        __nv_bfloat16* Sl = S_lo + (size_t)bc * EE * EE;
#pragma unroll
        for (int mt = 0; mt < 4; mt++)
#pragma unroll
            for (int h = 0; h < 2; h++) {
                int row = m0 + warp_m * 64 + mt * 16 + h * 8 + g;
#pragma unroll
                for (int nt = 0; nt < 8; nt++) {
                    int col = n0 + warp_n * 64 + nt * 8 + tg * 2;
                    uint32_t hi, lo;
                    split_pair(acc[mt][nt][2 * h], acc[mt][nt][2 * h + 1], hi, lo);
                    *(uint32_t*)&Sh[(size_t)row * EE + col] = hi;
                    *(uint32_t*)&Sl[(size_t)row * EE + col] = lo;
                }
            }
        // accumulate chunk c: acc += vT[:,chunk] * kT[:,chunk]^T
        gemm_block(acc, su,
                   vT_hi + ((size_t)b * EE + m0) * TT + (size_t)c * CC,
                   vT_lo + ((size_t)b * EE + m0) * TT + (size_t)c * CC,
                   kT_hi + ((size_t)b * EE + n0) * TT + (size_t)c * CC,
                   kT_lo + ((size_t)b * EE + n0) * TT + (size_t)c * CC,
                   TT, TT, 4);
    }
}

// ---------------------------------------------------------------------------
// A = causal-mask(Q K^T): rowsum -> g_rs, split bf16 -> A_hi/A_lo
// ---------------------------------------------------------------------------
__global__ __launch_bounds__(128, 2) void gemm_qk_kernel()
{
    extern __shared__ char sm[];
    __shared__ float s_rs[128][2];
    uint32_t su = smem_u32(sm);
    int bc = blockIdx.x, b = bc / NCH, c = bc % NCH;
    size_t base = ((size_t)b * TT + (size_t)c * CC) * EE;

    float acc[4][8][4];
    ZERO_ACC(acc);
    gemm_block(acc, su, q_hi + base, q_lo + base, k_hi + base, k_lo + base, EE, EE, 16);

    EPI_VARS;
    (void)lane;
    __nv_bfloat16* Ah = A_hi + (size_t)bc * CC * CC;
    __nv_bfloat16* Al = A_lo + (size_t)bc * CC * CC;
#pragma unroll
    for (int mt = 0; mt < 4; mt++)
#pragma unroll
        for (int h = 0; h < 2; h++) {
            int row = warp_m * 64 + mt * 16 + h * 8 + g;
            float rs = 0.f;
#pragma unroll
            for (int nt = 0; nt < 8; nt++) {
                int col = warp_n * 64 + nt * 8 + tg * 2;
                float v0 = acc[mt][nt][2 * h], v1 = acc[mt][nt][2 * h + 1];
                if (col > row) v0 = 0.f;
                if (col + 1 > row) v1 = 0.f;
                rs += v0 + v1;
                uint32_t hi, lo;
                split_pair(v0, v1, hi, lo);
                *(uint32_t*)&Ah[(size_t)row * CC + col] = hi;
                *(uint32_t*)&Al[(size_t)row * CC + col] = lo;
            }
            rs += __shfl_xor_sync(0xffffffffu, rs, 1);
            rs += __shfl_xor_sync(0xffffffffu, rs, 2);
            if (tg == 0) s_rs[row][warp_n] = rs;
        }
    __syncthreads();
    g_rs[(size_t)bc * CC + tid] = s_rs[tid][0] + s_rs[tid][1];
}

// ---------------------------------------------------------------------------
// out = (A @ V_c + Q @ S_c) / d, split -> at_hi/at_lo
// ---------------------------------------------------------------------------
__global__ __launch_bounds__(128, 2) void gemm_out_kernel()
{
    extern __shared__ char sm[];
    uint32_t su = smem_u32(sm);
    int n0 = blockIdx.x * 128;
    int bc = blockIdx.y, b = bc / NCH, c = bc % NCH;

    float acc[4][8][4];
    ZERO_ACC(acc);
    gemm_block(acc, su,
               A_hi + (size_t)bc * CC * CC, A_lo + (size_t)bc * CC * CC,
               vT_hi + ((size_t)b * EE + n0) * TT + (size_t)c * CC,
               vT_lo + ((size_t)b * EE + n0) * TT + (size_t)c * CC,
               CC, TT, 4);
    size_t qbase = ((size_t)b * TT + (size_t)c * CC) * EE;
    gemm_block(acc, su,
               q_hi + qbase, q_lo + qbase,
               S_hi + (size_t)bc * EE * EE + (size_t)n0 * EE,
               S_lo + (size_t)bc * EE * EE + (size_t)n0 * EE,
               EE, EE, 16);

    EPI_VARS;
    (void)tid; (void)lane;
#pragma unroll
    for (int mt = 0; mt < 4; mt++)
#pragma unroll
        for (int h = 0; h < 2; h++) {
            int row = warp_m * 64 + mt * 16 + h * 8 + g;
            float d = fmaxf(g_rs[(size_t)bc * CC + row] + g_dz[(size_t)bc * CC + row], EPSV);
            float inv = 1.0f / d;
            size_t ob = ((size_t)b * TT + (size_t)c * CC + row) * EE + n0;
#pragma unroll
            for (int nt = 0; nt < 8; nt++) {
                int col = warp_n * 64 + nt * 8 + tg * 2;
                uint32_t hi, lo;
                split_pair(acc[mt][nt][2 * h] * inv, acc[mt][nt][2 * h + 1] * inv, hi, lo);
                *(uint32_t*)&at_hi[ob + col] = hi;
                *(uint32_t*)&at_lo[ob + col] = lo;
            }
        }
}

// ---------------------------------------------------------------------------
// output projection -> d_out
// ---------------------------------------------------------------------------
__global__ __launch_bounds__(128, 2) void gemm_oproj_kernel(
    const float* __restrict__ ob_bias, float* __restrict__ outp)
{
    extern __shared__ char sm[];
    uint32_t su = smem_u32(sm);
    int m0 = blockIdx.x * 128, n0 = blockIdx.y * 128;

    float acc[4][8][4];
    ZERO_ACC(acc);
    gemm_block(acc, su,
               at_hi + (size_t)m0 * EE, at_lo + (size_t)m0 * EE,
               w_hi + (size_t)3 * EE * EE + (size_t)n0 * EE,
               w_lo + (size_t)3 * EE * EE + (size_t)n0 * EE,
               EE, EE, 16);

    EPI_VARS;
    (void)tid; (void)lane;
#pragma unroll
    for (int mt = 0; mt < 4; mt++)
#pragma unroll
        for (int h = 0; h < 2; h++) {
            int row = m0 + warp_m * 64 + mt * 16 + h * 8 + g;
#pragma unroll
            for (int nt = 0; nt < 8; nt++) {
                int col = n0 + warp_n * 64 + nt * 8 + tg * 2;
                float2 o;
                o.x = acc[mt][nt][2 * h] + ob_bias[col];
                o.y = acc[mt][nt][2 * h + 1] + ob_bias[col + 1];
                *(float2*)&outp[(size_t)row * EE + col] = o;
            }
        }
}

// ---------------------------------------------------------------------------
// conversion / elementwise kernels
// ---------------------------------------------------------------------------
__global__ __launch_bounds__(256) void conv_w_kernel(
    const float* __restrict__ qw, const float* __restrict__ kw,
    const float* __restrict__ vw, const float* __restrict__ ow)
{
    size_t idx = (size_t)blockIdx.x * 256 + threadIdx.x;
    if (idx >= (size_t)4 * EE * EE) return;
    int which = (int)(idx / ((size_t)EE * EE));
    size_t rem = idx % ((size_t)EE * EE);
    const float* w = (which == 0) ? qw : (which == 1) ? kw : (which == 2) ? vw : ow;
    float x = w[rem];
    __nv_bfloat16 h = __float2bfloat16(x);
    w_hi[idx] = h;
    w_lo[idx] = __float2bfloat16(x - __bfloat162float(h));
}

// x (B,E,T) fp32 -> xT (B,T,E) bf16 split
__global__ __launch_bounds__(256) void conv_xT_kernel(const float* __restrict__ x)
{
    __shared__ float ts[32][33];
    int b = blockIdx.z;
    int t0 = blockIdx.x * 32, e0 = blockIdx.y * 32;
    int tx = threadIdx.x, ty = threadIdx.y;  // (32,8)
    const float* xb = x + (size_t)b * EE * TT;
#pragma unroll
    for (int i = 0; i < 4; i++)
        ts[ty + i * 8][tx] = xb[(size_t)(e0 + ty + i * 8) * TT + t0 + tx];
    __syncthreads();
    size_t ob = (size_t)b * TT * EE;
#pragma unroll
    for (int i = 0; i < 4; i++) {
        float val = ts[tx][ty + i * 8];
        __nv_bfloat16 h = __float2bfloat16(val);
        size_t o = ob + (size_t)(t0 + ty + i * 8) * EE + e0 + tx;
        xT_hi[o] = h;
        xT_lo[o] = __float2bfloat16(val - __bfloat162float(h));
    }
}

// q softmax + split
__global__ __launch_bounds__(128) void act_kernel()
{
    int bt = blockIdx.x;
    int tid = threadIdx.x;
    size_t base = (size_t)bt * EE;
    __shared__ float sred[4];

    float qv[4];
#pragma unroll
    for (int u = 0; u < 4; u++) qv[u] = g_q[base + tid + u * 128];
    float m = fmaxf(fmaxf(qv[0], qv[1]), fmaxf(qv[2], qv[3]));
#pragma unroll
    for (int o = 16; o; o >>= 1) m = fmaxf(m, __shfl_xor_sync(0xffffffffu, m, o));
    if ((tid & 31) == 0) sred[tid >> 5] = m;
    __syncthreads();
    m = fmaxf(fmaxf(sred[0], sred[1]), fmaxf(sred[2], sred[3]));
    __syncthreads();
    float s = 0.f;
#pragma unroll
    for (int u = 0; u < 4; u++) { qv[u] = expf(qv[u] - m); s += qv[u]; }
#pragma unroll
    for (int o = 16; o; o >>= 1) s += __shfl_xor_sync(0xffffffffu, s, o);
    if ((tid & 31) == 0) sred[tid >> 5] = s;
    __syncthreads();
    s = sred[0] + sred[1] + sred[2] + sred[3];
    float scale = INV_SQRT_E / s;
#pragma unroll
    for (int u = 0; u < 4; u++) {
        size_t idx = base + tid + u * 128;
        float val = qv[u] * scale;
        __nv_bfloat16 h = __float2bfloat16(val);
        q_hi[idx] = h;
        q_lo[idx] = __float2bfloat16(val - __bfloat162float(h));
    }
}

__global__ __launch_bounds__(128) void zprefix_kernel()
{
    int idx = blockIdx.x * blockDim.x + threadIdx.x;
    if (idx >= BB * EE) return;
    int b = idx / EE, off = idx % EE;
    float run = 0.f;
    float* p = g_z + (size_t)b * NCH * EE + off;
#pragma unroll
    for (int c = 0; c < NCH; c++) {
        float tmp = *p; *p = run; run += tmp; p += EE;
    }
}

// dz[b,c,i] = sum_e q[b, c*128+i, e] * z_excl[b,c,e]   (q from split)
__global__ __launch_bounds__(256) void dz_kernel()
{
    int bc = blockIdx.x;
    int b = bc / NCH, c = bc % NCH;
    int w = threadIdx.x >> 5, lane = threadIdx.x & 31;
    const float* z = g_z + (size_t)bc * EE;
#pragma unroll
    for (int it = 0; it < 16; it++) {
        int i = it * 8 + w;
        size_t qrow = ((size_t)b * TT + (size_t)c * CC + i) * EE;
        float s = 0.f;
#pragma unroll 4
        for (int j = lane; j < EE; j += 32) {
            float qv = __bfloat162float(q_hi[qrow + j]) + __bfloat162float(q_lo[qrow + j]);
            s += qv * z[j];
        }
#pragma unroll
        for (int o = 16; o; o >>= 1) s += __shfl_xor_sync(0xffffffffu, s, o);
        if (lane == 0) g_dz[(size_t)bc * CC + i] = s;
    }
}

// ---------------------------------------------------------------------------
extern "C" void kernel_launch(void* const* d_in, const int* in_sizes, int n_in,
                              void* d_out, int out_size)
{
    const float* x    = (const float*)d_in[0];
    const float* toep = (const float*)d_in[1];
    const float* qw   = (const float*)d_in[2];
    const float* qb   = (const float*)d_in[3];
    const float* kw   = (const float*)d_in[4];
    const float* kb   = (const float*)d_in[5];
    const float* vw   = (const float*)d_in[6];
    const float* vb   = (const float*)d_in[7];
    const float* ow   = (const float*)d_in[8];
    const float* ob   = (const float*)d_in[9];
    float* out = (float*)d_out;

    static cudaStream_t s_aux = nullptr;
    static cudaEvent_t ev_fork = nullptr, ev_join = nullptr;
    static int attr_done = 0;
    if (!attr_done) {
        cudaFuncSetAttribute(gemm_proj_kernel,  cudaFuncAttributeMaxDynamicSharedMemorySize, SMEM_BYTES);
        cudaFuncSetAttribute(gemm_hscan_kernel, cudaFuncAttributeMaxDynamicSharedMemorySize, SMEM_BYTES);
        cudaFuncSetAttribute(gemm_qk_kernel,    cudaFuncAttributeMaxDynamicSharedMemorySize, SMEM_BYTES);
        cudaFuncSetAttribute(gemm_out_kernel,   cudaFuncAttributeMaxDynamicSharedMemorySize, SMEM_BYTES);
        cudaFuncSetAttribute(gemm_oproj_kernel, cudaFuncAttributeMaxDynamicSharedMemorySize, SMEM_BYTES);
        cudaStreamCreateWithFlags(&s_aux, cudaStreamNonBlocking);
        cudaEventCreateWithFlags(&ev_fork, cudaEventDisableTiming);
        cudaEventCreateWithFlags(&ev_join, cudaEventDisableTiming);
        attr_done = 1;
    }

    conv_w_kernel<<<(int)(((size_t)4 * EE * EE + 255) / 256), 256>>>(qw, kw, vw, ow);
    conv_xT_kernel<<<dim3(TT / 32, EE / 32, BB), dim3(32, 8)>>>(x);

    gemm_proj_kernel<<<dim3(BB * TT / 128, EE / 128, 3), 128, SMEM_BYTES>>>(qb, kb, vb, toep);
    act_kernel<<<BB * TT, 128>>>();
    zprefix_kernel<<<(BB * EE + 127) / 128, 128>>>();

    // fork: run qk + dz on aux stream concurrently with the state scan
    cudaEventRecord(ev_fork, 0);
    cudaStreamWaitEvent(s_aux, ev_fork, 0);

    gemm_hscan_kernel<<<dim3(EE / 128, EE / 128, BB), 128, SMEM_BYTES>>>();

    gemm_qk_kernel<<<BB * NCH, 128, SMEM_BYTES, s_aux>>>();
    dz_kernel<<<BB * NCH, 256, 0, s_aux>>>();

    cudaEventRecord(ev_join, s_aux);
    cudaStreamWaitEvent(0, ev_join, 0);

    gemm_out_kernel<<<dim3(EE / 128, BB * NCH), 128, SMEM_BYTES>>>();
    gemm_oproj_kernel<<<dim3(BB * TT / 128, EE / 128), 128, SMEM_BYTES>>>(ob, out);
}